// round 12
// baseline (speedup 1.0000x reference)
#include <cuda_runtime.h>
#include <cuda_bf16.h>
#include <math.h>
#include <stdint.h>

// B=2, T=4096, HID=2048, H=16, D=128, ROPE_DIM=64, CHUNK=64, nc=64
typedef unsigned long long ull;

// ---------------------------------------------------------------------------
// Scratch (device globals; allocation is forbidden)
// ---------------------------------------------------------------------------
__device__ float g_qkv [50331648];  // [8192][6144]  q|k|v
__device__ float g_gate[16777216];  // [8192][2048]  sigmoid(gate)
__device__ float g_kv  [33554432];  // [B*H*64][128][128] chunk KV -> in-place S_c
__device__ float g_rope[  524288];  // [8192][64] cos|sin

// bf16 split buffers
__device__ __nv_bfloat16 g_hhi[16777216], g_hlo[16777216];   // hidden
__device__ __nv_bfloat16 g_qwhi[12582912], g_qwlo[12582912]; // w_qkv
__device__ __nv_bfloat16 g_gwhi[4194304],  g_gwlo[4194304];  // w_g_proj
__device__ __nv_bfloat16 g_dwhi[4194304],  g_dwlo[4194304];  // w_dense
__device__ __nv_bfloat16 g_xhi[16777216],  g_xlo[16777216];  // gated O

__device__ __forceinline__ float head_slope(int h) {
    const float LSCALE = 0.6451712903225806f;   // 1 - 11/31 + 1e-5
    return -exp2f(-0.5f * (float)(h + 1)) * LSCALE;
}

// ---------------------------------------------------------------------------
// Packed f32x2 helpers (attention-side kernels)
// ---------------------------------------------------------------------------
__device__ __forceinline__ ull pk2(float lo, float hi) {
    ull r; asm("mov.b64 %0,{%1,%2};" : "=l"(r) : "f"(lo), "f"(hi)); return r;
}
__device__ __forceinline__ void upk2(ull v, float& lo, float& hi) {
    asm("mov.b64 {%0,%1},%2;" : "=f"(lo), "=f"(hi) : "l"(v));
}
__device__ __forceinline__ void fma2(ull& d, ull a, ull b) {
    asm("fma.rn.f32x2 %0,%1,%2,%0;" : "+l"(d) : "l"(a), "l"(b));
}

// ---------------------------------------------------------------------------
// cp.async / ldmatrix / mma primitives (all arch-agnostic: sm_80+)
// ---------------------------------------------------------------------------
__device__ __forceinline__ uint32_t smem_u32(const void* p) {
    uint32_t a;
    asm("{ .reg .u64 t; cvta.to.shared.u64 t, %1; cvt.u32.u64 %0, t; }" : "=r"(a) : "l"(p));
    return a;
}
__device__ __forceinline__ void cpa16(uint32_t dst, const void* src) {
    asm volatile("cp.async.cg.shared.global [%0], [%1], 16;" :: "r"(dst), "l"(src));
}
#define CP_COMMIT() asm volatile("cp.async.commit_group;" ::: "memory")

#define LDSM4(r, a)                                                             \
    asm volatile("ldmatrix.sync.aligned.m8n8.x4.shared.b16 {%0,%1,%2,%3}, [%4];"\
        : "=r"((r)[0]), "=r"((r)[1]), "=r"((r)[2]), "=r"((r)[3]) : "r"(a))

__device__ __forceinline__ void mma16816(float* c, const uint32_t* a, const uint32_t* b) {
    asm volatile("mma.sync.aligned.m16n8k16.row.col.f32.bf16.bf16.f32 "
        "{%0,%1,%2,%3},{%4,%5,%6,%7},{%8,%9},{%0,%1,%2,%3};"
        : "+f"(c[0]), "+f"(c[1]), "+f"(c[2]), "+f"(c[3])
        : "r"(a[0]), "r"(a[1]), "r"(a[2]), "r"(a[3]), "r"(b[0]), "r"(b[1]));
}

// ---------------------------------------------------------------------------
// fp32 -> bf16 hi/lo split (4 elems/thread)
// ---------------------------------------------------------------------------
__global__ void __launch_bounds__(256) split4(
    const float* __restrict__ x, __nv_bfloat16* __restrict__ hi,
    __nv_bfloat16* __restrict__ lo, int n4)
{
    int i = blockIdx.x * 256 + threadIdx.x;
    if (i >= n4) return;
    float4 v = ((const float4*)x)[i];
    __nv_bfloat162 h01 = __floats2bfloat162_rn(v.x, v.y);
    __nv_bfloat162 h23 = __floats2bfloat162_rn(v.z, v.w);
    float r0 = v.x - __low2float(h01), r1 = v.y - __high2float(h01);
    float r2 = v.z - __low2float(h23), r3 = v.w - __high2float(h23);
    __nv_bfloat162 l01 = __floats2bfloat162_rn(r0, r1);
    __nv_bfloat162 l23 = __floats2bfloat162_rn(r2, r3);
    uint2 hp, lp;
    hp.x = *(unsigned*)&h01; hp.y = *(unsigned*)&h23;
    lp.x = *(unsigned*)&l01; lp.y = *(unsigned*)&l23;
    ((uint2*)hi)[i] = hp;
    ((uint2*)lo)[i] = lp;
}

// ---------------------------------------------------------------------------
// HMMA GEMM NT (fp32-split bf16): C[M,N] = (Ahi+Alo)[M,K] @ (Bhi+Blo)[N,K]^T
// 128x128 CTA tile, 8 warps x (32m x 64n), K-chunk 32.
// v3: 2-stage double buffer (80KB) + __launch_bounds__(256,2) so TWO CTAs
// co-reside per SM and hide each other's sync/ldmatrix bubbles.
// Per stage (40960B): Ahi@0, Alo@10240, Bhi@20480, Blo@30720; rows 64B data,
// 80B stride (conflict-free ldmatrix phases). Split: hi*hi + lo*hi + hi*lo.
// ---------------------------------------------------------------------------
static constexpr int STG = 40960;
template<bool SIG>
__global__ void __launch_bounds__(256, 2) hgemm(
    const __nv_bfloat16* __restrict__ Ahi, const __nv_bfloat16* __restrict__ Alo,
    const __nv_bfloat16* __restrict__ Bhi, const __nv_bfloat16* __restrict__ Blo,
    float* __restrict__ C, int M, int N, int K)
{
    extern __shared__ char smem[];
    const uint32_t sb = smem_u32(smem);
    const int tid = threadIdx.x, wid = tid >> 5, lane = tid & 31;
    const int bm = blockIdx.y * 128, bn = blockIdx.x * 128;
    const int wm = (wid & 3) * 32, wn = (wid >> 2) * 64;
    const int NC = K >> 5;

    const char* gAh = (const char*)(Ahi + (size_t)bm * K);
    const char* gAl = (const char*)(Alo + (size_t)bm * K);
    const char* gBh = (const char*)(Bhi + (size_t)bn * K);
    const char* gBl = (const char*)(Blo + (size_t)bn * K);
    const size_t grs = (size_t)K * 2;

    auto load = [&](int c, int s) {
        uint32_t stg = sb + s * STG;
        size_t ko = (size_t)c * 64;
#pragma unroll
        for (int i = 0; i < 2; i++) {
            int u = tid + 256 * i;
            int r = u >> 2; uint32_t q = (uint32_t)(u & 3) * 16;
            uint32_t so = (uint32_t)r * 80 + q;
            size_t go = (size_t)r * grs + ko + q;
            cpa16(stg + so,         gAh + go);
            cpa16(stg + 10240 + so, gAl + go);
            cpa16(stg + 20480 + so, gBh + go);
            cpa16(stg + 30720 + so, gBl + go);
        }
        CP_COMMIT();
    };

    float acc[2][8][4];
#pragma unroll
    for (int mt = 0; mt < 2; mt++)
#pragma unroll
        for (int nt = 0; nt < 8; nt++)
#pragma unroll
            for (int j = 0; j < 4; j++) acc[mt][nt][j] = 0.f;

    load(0, 0);
    load(1, 1);

    const uint32_t arow = (uint32_t)(wm + (lane & 15));
    const uint32_t brow = (uint32_t)(wn + (lane & 7) + ((lane >> 4) << 3));

    for (int c = 0; c < NC; c++) {
        if (c + 1 < NC) asm volatile("cp.async.wait_group 1;" ::: "memory");
        else            asm volatile("cp.async.wait_group 0;" ::: "memory");
        __syncthreads();
        uint32_t stg = sb + (c & 1) * STG;
#pragma unroll
        for (int s = 0; s < 2; s++) {
            uint32_t colA = (uint32_t)s * 32 + ((lane >> 4) << 4);
            uint32_t colB = (uint32_t)s * 32 + (((lane >> 3) & 1) << 4);
            uint32_t aA = stg + arow * 80 + colA;
            uint32_t aB = stg + 20480 + brow * 80 + colB;
            uint32_t ah[2][4], al[2][4], bb[4][4];
            LDSM4(ah[0], aA);
            LDSM4(ah[1], aA + 16 * 80);
#pragma unroll
            for (int p = 0; p < 4; p++) LDSM4(bb[p], aB + p * 16 * 80);
            // hi*hi
#pragma unroll
            for (int mt = 0; mt < 2; mt++)
#pragma unroll
                for (int nt = 0; nt < 8; nt++)
                    mma16816(acc[mt][nt], ah[mt], &bb[nt >> 1][(nt & 1) * 2]);
            // lo*hi
            LDSM4(al[0], aA + 10240);
            LDSM4(al[1], aA + 10240 + 16 * 80);
#pragma unroll
            for (int mt = 0; mt < 2; mt++)
#pragma unroll
                for (int nt = 0; nt < 8; nt++)
                    mma16816(acc[mt][nt], al[mt], &bb[nt >> 1][(nt & 1) * 2]);
            // hi*lo
#pragma unroll
            for (int p = 0; p < 4; p++) LDSM4(bb[p], aB + 10240 + p * 16 * 80);
#pragma unroll
            for (int mt = 0; mt < 2; mt++)
#pragma unroll
                for (int nt = 0; nt < 8; nt++)
                    mma16816(acc[mt][nt], ah[mt], &bb[nt >> 1][(nt & 1) * 2]);
        }
        __syncthreads();
        if (c + 2 < NC) load(c + 2, c & 1);
    }

    // epilogue: c0,c1 -> C[g][2tg..], c2,c3 -> C[g+8][2tg..]
    const int g = lane >> 2, tg = lane & 3;
#pragma unroll
    for (int mt = 0; mt < 2; mt++) {
        int m0 = bm + wm + mt * 16 + g;
#pragma unroll
        for (int nt = 0; nt < 8; nt++) {
            int n0 = bn + wn + nt * 8 + tg * 2;
            float v0 = acc[mt][nt][0], v1 = acc[mt][nt][1];
            float v2 = acc[mt][nt][2], v3 = acc[mt][nt][3];
            if (SIG) {
                v0 = 1.f / (1.f + expf(-v0)); v1 = 1.f / (1.f + expf(-v1));
                v2 = 1.f / (1.f + expf(-v2)); v3 = 1.f / (1.f + expf(-v3));
            }
            float2* p0 = (float2*)(C + (size_t)m0 * N + n0);
            float2* p1 = (float2*)(C + (size_t)(m0 + 8) * N + n0);
            *p0 = make_float2(v0, v1);
            *p1 = make_float2(v2, v3);
        }
    }
}

// ---------------------------------------------------------------------------
// RoPE cos/sin table (fp64 angles)
// ---------------------------------------------------------------------------
__global__ void rope_table(const int* __restrict__ pos, float* __restrict__ rope)
{
    int idx = blockIdx.x * 256 + threadIdx.x;
    int bt = idx >> 5, i = idx & 31;
    double invf = pow(10000.0, -(double)(2 * i) / 64.0);
    double ang  = (double)pos[bt] * invf;
    double sd, cd; sincos(ang, &sd, &cd);
    rope[bt * 64 + i]      = (float)cd;
    rope[bt * 64 + 32 + i] = (float)sd;
}

// ---------------------------------------------------------------------------
// Per-head RMSNorm + RoPE on q,k in place (warp per (bt,h)); q *= D^-1/2.
// ---------------------------------------------------------------------------
__global__ void __launch_bounds__(256) norm_rope(
    float* __restrict__ qkv, const float* __restrict__ qw,
    const float* __restrict__ kw, const float* __restrict__ rope)
{
    int gw   = blockIdx.x * 8 + (threadIdx.x >> 5);
    int lane = threadIdx.x & 31;
    int bt = gw >> 4, h = gw & 15;
    float* qrow = qkv + (size_t)bt * 6144 + h * 128;
    const float* rc = rope + bt * 64;

    float c4[4], s4[4];
    if (lane < 16) {
#pragma unroll
        for (int m = 0; m < 4; m++) {
            int fi = (lane * 4 + m) & 31;
            c4[m] = rc[fi]; s4[m] = rc[32 + fi];
        }
    }
    float sgn = (lane < 8) ? -1.f : 1.f;

#pragma unroll
    for (int pass = 0; pass < 2; pass++) {
        float* row = qrow + pass * 2048;
        const float* wv = pass ? kw : qw;
        float4 x = *(float4*)(row + lane * 4);
        float ss = x.x * x.x + x.y * x.y + x.z * x.z + x.w * x.w;
#pragma unroll
        for (int off = 16; off >= 1; off >>= 1) ss += __shfl_xor_sync(0xffffffffu, ss, off);
        float r = rsqrtf(ss * (1.f / 128.f) + 1e-6f);
        float4 w4 = *(const float4*)(wv + lane * 4);
        x.x *= r * w4.x; x.y *= r * w4.y; x.z *= r * w4.z; x.w *= r * w4.w;
        float px = __shfl_xor_sync(0xffffffffu, x.x, 8);
        float py = __shfl_xor_sync(0xffffffffu, x.y, 8);
        float pz = __shfl_xor_sync(0xffffffffu, x.z, 8);
        float pw = __shfl_xor_sync(0xffffffffu, x.w, 8);
        if (lane < 16) {
            x.x = x.x * c4[0] + sgn * px * s4[0];
            x.y = x.y * c4[1] + sgn * py * s4[1];
            x.z = x.z * c4[2] + sgn * pz * s4[2];
            x.w = x.w * c4[3] + sgn * pw * s4[3];
        }
        if (pass == 0) {
            const float qs = 0.08838834764831845f;
            x.x *= qs; x.y *= qs; x.z *= qs; x.w *= qs;
        }
        *(float4*)(row + lane * 4) = x;
    }
}

// ---------------------------------------------------------------------------
// Per-chunk decayed KV outer product (f32x2)
// ---------------------------------------------------------------------------
__global__ void __launch_bounds__(256) kv_outer(
    const float* __restrict__ qkv, float* __restrict__ kv)
{
    extern __shared__ __align__(16) float sm[];
    float* Ks = sm;
    float* Vs = sm + 64 * 132;
    int c = blockIdx.x, bh = blockIdx.y;
    int b = bh >> 4, h = bh & 15;
    float g = head_slope(h);
    int tid = threadIdx.x;

    int li = tid >> 2, lc = (tid & 3) * 32;
    const float* krow = qkv + (size_t)(b * 4096 + c * 64 + li) * 6144 + 2048 + h * 128;
    float kd = expf(g * (float)(63 - li));
#pragma unroll
    for (int u = 0; u < 8; u++) {
        float4 kk = *(const float4*)(krow + lc + u * 4);
        kk.x *= kd; kk.y *= kd; kk.z *= kd; kk.w *= kd;
        *(float4*)&Ks[li * 132 + lc + u * 4] = kk;
        *(float4*)&Vs[li * 132 + lc + u * 4] = *(const float4*)(krow + 2048 + lc + u * 4);
    }
    __syncthreads();

    int tx = tid & 15, ty = tid >> 4;
    int d0 = ty * 8, e0 = tx * 8;
    ull acc[8][4];
#pragma unroll
    for (int i = 0; i < 8; i++)
#pragma unroll
        for (int j = 0; j < 4; j++) acc[i][j] = 0ull;

    for (int i = 0; i < 64; i++) {
        float4 k0 = *(const float4*)&Ks[i * 132 + d0];
        float4 k1 = *(const float4*)&Ks[i * 132 + d0 + 4];
        float4 v0 = *(const float4*)&Vs[i * 132 + e0];
        float4 v1 = *(const float4*)&Vs[i * 132 + e0 + 4];
        ull vv[4] = { pk2(v0.x, v0.y), pk2(v0.z, v0.w), pk2(v1.x, v1.y), pk2(v1.z, v1.w) };
        float km[8] = { k0.x, k0.y, k0.z, k0.w, k1.x, k1.y, k1.z, k1.w };
#pragma unroll
        for (int di = 0; di < 8; di++) {
            ull aa = pk2(km[di], km[di]);
#pragma unroll
            for (int j = 0; j < 4; j++) fma2(acc[di][j], aa, vv[j]);
        }
    }
    size_t base = (size_t)(bh * 64 + c) * 16384;
#pragma unroll
    for (int di = 0; di < 8; di++) {
        float o[8];
#pragma unroll
        for (int j = 0; j < 4; j++) upk2(acc[di][j], o[2 * j], o[2 * j + 1]);
        float* op = kv + base + (size_t)(d0 + di) * 128 + e0;
        *(float4*)op       = make_float4(o[0], o[1], o[2], o[3]);
        *(float4*)(op + 4) = make_float4(o[4], o[5], o[6], o[7]);
    }
}

// ---------------------------------------------------------------------------
// In-place decay scan over kv: writes pre-state S_c
// ---------------------------------------------------------------------------
__global__ void __launch_bounds__(256) scan_states(float* __restrict__ kv)
{
    int t  = blockIdx.x * 256 + threadIdx.x;
    int bh = t >> 14, de = t & 16383;
    float dec = expf(head_slope(bh & 15) * 64.f);
    size_t base = (size_t)bh * 64 * 16384 + de;
    float st = 0.f;
#pragma unroll 1
    for (int c = 0; c < 64; c++) {
        float kvv = kv[base + (size_t)c * 16384];
        kv[base + (size_t)c * 16384] = st;
        st = dec * st + kvv;
    }
}

// ---------------------------------------------------------------------------
// Per-chunk output: O = (mask .* QK^T) V + diag(exp(g*(i+1))) Q S_c
// ---------------------------------------------------------------------------
__global__ void __launch_bounds__(256) gla_out(
    float* __restrict__ qkv, const float* __restrict__ S)
{
    extern __shared__ __align__(16) float sm[];
    float* Qs  = sm;
    float* KVs = sm + 8448;
    float* Att = sm + 16896;
    float* St  = sm + 21248;
    int c = blockIdx.x, bh = blockIdx.y;
    int b = bh >> 4, h = bh & 15;
    float g = head_slope(h);
    int tid = threadIdx.x;

    int li = tid >> 2, lc = (tid & 3) * 32;
    const float* qrowL = qkv + (size_t)(b * 4096 + c * 64 + li) * 6144 + h * 128;
#pragma unroll
    for (int u = 0; u < 8; u++) {
        *(float4*)&Qs [li * 132 + lc + u * 4] = *(const float4*)(qrowL + lc + u * 4);
        *(float4*)&KVs[li * 132 + lc + u * 4] = *(const float4*)(qrowL + 2048 + lc + u * 4);
    }
    __syncthreads();

    int tx = tid & 15, ty = tid >> 4;
    {
        int i0 = ty * 4, j0 = tx * 4;
        float a[4][4];
#pragma unroll
        for (int ii = 0; ii < 4; ii++)
#pragma unroll
            for (int jj = 0; jj < 4; jj++) a[ii][jj] = 0.f;
        for (int d = 0; d < 128; d += 4) {
            float4 qv[4], kv4[4];
#pragma unroll
            for (int ii = 0; ii < 4; ii++) qv[ii]  = *(const float4*)&Qs [(i0 + ii) * 132 + d];
#pragma unroll
            for (int jj = 0; jj < 4; jj++) kv4[jj] = *(const float4*)&KVs[(j0 + jj) * 132 + d];
#pragma unroll
            for (int ii = 0; ii < 4; ii++)
#pragma unroll
                for (int jj = 0; jj < 4; jj++)
                    a[ii][jj] += qv[ii].x * kv4[jj].x + qv[ii].y * kv4[jj].y
                               + qv[ii].z * kv4[jj].z + qv[ii].w * kv4[jj].w;
        }
#pragma unroll
        for (int ii = 0; ii < 4; ii++)
#pragma unroll
            for (int jj = 0; jj < 4; jj++) {
                int i = i0 + ii, j = j0 + jj;
                Att[i * 68 + j] = (i >= j) ? a[ii][jj] * expf(g * (float)(i - j)) : 0.f;
            }
    }
    __syncthreads();
#pragma unroll
    for (int u = 0; u < 8; u++)
        *(float4*)&KVs[li * 132 + lc + u * 4] = *(const float4*)(qrowL + 4096 + lc + u * 4);

    int i0 = ty * 4, e0 = tx * 8;
    ull acc[4][4];
#pragma unroll
    for (int ii = 0; ii < 4; ii++)
#pragma unroll
        for (int j = 0; j < 4; j++) acc[ii][j] = 0ull;

    size_t sbase2 = (size_t)(bh * 64 + c) * 16384;
    int sr = tid >> 4, sc = (tid & 15) * 8;
    for (int dt = 0; dt < 8; dt++) {
        __syncthreads();
        *(float4*)&St[sr * 132 + sc]     = *(const float4*)(S + sbase2 + (size_t)(dt * 16 + sr) * 128 + sc);
        *(float4*)&St[sr * 132 + sc + 4] = *(const float4*)(S + sbase2 + (size_t)(dt * 16 + sr) * 128 + sc + 4);
        __syncthreads();
#pragma unroll
        for (int d = 0; d < 16; d++) {
            float4 s0 = *(const float4*)&St[d * 132 + e0];
            float4 s1 = *(const float4*)&St[d * 132 + e0 + 4];
            ull ss[4] = { pk2(s0.x, s0.y), pk2(s0.z, s0.w), pk2(s1.x, s1.y), pk2(s1.z, s1.w) };
#pragma unroll
            for (int ii = 0; ii < 4; ii++) {
                float q = Qs[(i0 + ii) * 132 + dt * 16 + d];
                ull aa = pk2(q, q);
#pragma unroll
                for (int j = 0; j < 4; j++) fma2(acc[ii][j], aa, ss[j]);
            }
        }
    }
#pragma unroll
    for (int ii = 0; ii < 4; ii++) {
        float qd = expf(g * (float)(i0 + ii + 1));
#pragma unroll
        for (int j = 0; j < 4; j++) {
            float lo, hi; upk2(acc[ii][j], lo, hi);
            acc[ii][j] = pk2(lo * qd, hi * qd);
        }
    }
#pragma unroll 4
    for (int j = 0; j < 64; j++) {
        float4 v0 = *(const float4*)&KVs[j * 132 + e0];
        float4 v1 = *(const float4*)&KVs[j * 132 + e0 + 4];
        ull vv[4] = { pk2(v0.x, v0.y), pk2(v0.z, v0.w), pk2(v1.x, v1.y), pk2(v1.z, v1.w) };
#pragma unroll
        for (int ii = 0; ii < 4; ii++) {
            float a = Att[(i0 + ii) * 68 + j];
            ull aa = pk2(a, a);
#pragma unroll
            for (int jj = 0; jj < 4; jj++) fma2(acc[ii][jj], aa, vv[jj]);
        }
    }
#pragma unroll
    for (int ii = 0; ii < 4; ii++) {
        float o[8];
#pragma unroll
        for (int j = 0; j < 4; j++) upk2(acc[ii][j], o[2 * j], o[2 * j + 1]);
        float* orow = qkv + (size_t)(b * 4096 + c * 64 + i0 + ii) * 6144 + 4096 + h * 128 + e0;
        *(float4*)orow       = make_float4(o[0], o[1], o[2], o[3]);
        *(float4*)(orow + 4) = make_float4(o[4], o[5], o[6], o[7]);
    }
}

// ---------------------------------------------------------------------------
// Group RMSNorm * g_norm_w * sigmoid-gate -> bf16 hi/lo split (fused)
// ---------------------------------------------------------------------------
__global__ void __launch_bounds__(256) gate_norm(
    const float* __restrict__ qkv, const float* __restrict__ gate,
    const float* __restrict__ gw,
    __nv_bfloat16* __restrict__ xhi, __nv_bfloat16* __restrict__ xlo)
{
    int gwid = blockIdx.x * 8 + (threadIdx.x >> 5);
    int lane = threadIdx.x & 31;
    int bt = gwid >> 4, h = gwid & 15;
    const float* orow = qkv + (size_t)bt * 6144 + 4096 + h * 128;
    float4 x = *(const float4*)(orow + lane * 4);
    float ss = x.x * x.x + x.y * x.y + x.z * x.z + x.w * x.w;
#pragma unroll
    for (int off = 16; off >= 1; off >>= 1) ss += __shfl_xor_sync(0xffffffffu, ss, off);
    float r = rsqrtf(ss * (1.f / 128.f) + 1e-6f);
    float4 w  = *(const float4*)(gw + h * 128 + lane * 4);
    size_t idx = (size_t)bt * 2048 + h * 128 + lane * 4;
    float4 gt = *(const float4*)(gate + idx);
    float4 o;
    o.x = x.x * r * w.x * gt.x;
    o.y = x.y * r * w.y * gt.y;
    o.z = x.z * r * w.z * gt.z;
    o.w = x.w * r * w.w * gt.w;
    __nv_bfloat162 h01 = __floats2bfloat162_rn(o.x, o.y);
    __nv_bfloat162 h23 = __floats2bfloat162_rn(o.z, o.w);
    float r0 = o.x - __low2float(h01), r1 = o.y - __high2float(h01);
    float r2 = o.z - __low2float(h23), r3 = o.w - __high2float(h23);
    __nv_bfloat162 l01 = __floats2bfloat162_rn(r0, r1);
    __nv_bfloat162 l23 = __floats2bfloat162_rn(r2, r3);
    uint2 hp, lp;
    hp.x = *(unsigned*)&h01; hp.y = *(unsigned*)&h23;
    lp.x = *(unsigned*)&l01; lp.y = *(unsigned*)&l23;
    *(uint2*)(xhi + idx) = hp;
    *(uint2*)(xlo + idx) = lp;
}

// ---------------------------------------------------------------------------
extern "C" void kernel_launch(void* const* d_in, const int* in_sizes, int n_in,
                              void* d_out, int out_size)
{
    const float* hidden   = (const float*)d_in[0];
    const float* w_qkv    = (const float*)d_in[1];
    const float* q_ln_w   = (const float*)d_in[2];
    const float* k_ln_w   = (const float*)d_in[3];
    const float* g_norm_w = (const float*)d_in[4];
    const float* w_g_proj = (const float*)d_in[5];
    const float* w_dense  = (const float*)d_in[6];
    const int*   pos_ids  = (const int*)d_in[7];
    float* out = (float*)d_out;
    (void)in_sizes; (void)n_in; (void)out_size;

    float *qkv, *gate, *kv, *rope;
    cudaGetSymbolAddress((void**)&qkv,  g_qkv);
    cudaGetSymbolAddress((void**)&gate, g_gate);
    cudaGetSymbolAddress((void**)&kv,   g_kv);
    cudaGetSymbolAddress((void**)&rope, g_rope);
    __nv_bfloat16 *hhi, *hlo, *qwhi, *qwlo, *gwhi, *gwlo, *dwhi, *dwlo, *xhi, *xlo;
    cudaGetSymbolAddress((void**)&hhi,  g_hhi);  cudaGetSymbolAddress((void**)&hlo,  g_hlo);
    cudaGetSymbolAddress((void**)&qwhi, g_qwhi); cudaGetSymbolAddress((void**)&qwlo, g_qwlo);
    cudaGetSymbolAddress((void**)&gwhi, g_gwhi); cudaGetSymbolAddress((void**)&gwlo, g_gwlo);
    cudaGetSymbolAddress((void**)&dwhi, g_dwhi); cudaGetSymbolAddress((void**)&dwlo, g_dwlo);
    cudaGetSymbolAddress((void**)&xhi,  g_xhi);  cudaGetSymbolAddress((void**)&xlo,  g_xlo);

    cudaFuncSetAttribute(kv_outer, cudaFuncAttributeMaxDynamicSharedMemorySize, 67584);
    cudaFuncSetAttribute(gla_out,  cudaFuncAttributeMaxDynamicSharedMemorySize, 93440);
    cudaFuncSetAttribute(hgemm<false>, cudaFuncAttributeMaxDynamicSharedMemorySize, 2 * STG);
    cudaFuncSetAttribute(hgemm<true>,  cudaFuncAttributeMaxDynamicSharedMemorySize, 2 * STG);

    rope_table<<<1024, 256>>>(pos_ids, rope);
    split4<<<16384, 256>>>(hidden,   hhi,  hlo,  4194304);
    split4<<<12288, 256>>>(w_qkv,    qwhi, qwlo, 3145728);
    split4<<< 4096, 256>>>(w_g_proj, gwhi, gwlo, 1048576);
    split4<<< 4096, 256>>>(w_dense,  dwhi, dwlo, 1048576);

    hgemm<false><<<dim3(48, 64), 256, 2 * STG>>>(hhi, hlo, qwhi, qwlo, qkv, 8192, 6144, 2048);
    norm_rope<<<16384, 256>>>(qkv, q_ln_w, k_ln_w, rope);
    kv_outer<<<dim3(64, 32), 256, 67584>>>(qkv, kv);
    scan_states<<<2048, 256>>>(kv);
    gla_out<<<dim3(64, 32), 256, 93440>>>(qkv, kv);
    hgemm<true><<<dim3(16, 64), 256, 2 * STG>>>(hhi, hlo, gwhi, gwlo, gate, 8192, 2048, 2048);
    gate_norm<<<16384, 256>>>(qkv, gate, g_norm_w, xhi, xlo);
    hgemm<false><<<dim3(16, 64), 256, 2 * STG>>>(xhi, xlo, dwhi, dwlo, out, 8192, 2048, 2048);
}

// round 13
// speedup vs baseline: 1.1019x; 1.1019x over previous
#include <cuda_runtime.h>
#include <cuda_bf16.h>
#include <math.h>
#include <stdint.h>

// B=2, T=4096, HID=2048, H=16, D=128, ROPE_DIM=64, CHUNK=64, nc=64
typedef unsigned long long ull;

// ---------------------------------------------------------------------------
// Scratch (device globals; allocation is forbidden)
// ---------------------------------------------------------------------------
__device__ float g_qkv [50331648];  // [8192][6144]  q|k|v
__device__ float g_gate[16777216];  // [8192][2048]  sigmoid(gate)
__device__ float g_kv  [33554432];  // [B*H*64][128][128] chunk KV -> in-place S_c
__device__ float g_rope[  524288];  // [8192][64] cos|sin

// bf16 split buffers
__device__ __nv_bfloat16 g_hhi[16777216], g_hlo[16777216];   // hidden
__device__ __nv_bfloat16 g_qwhi[12582912], g_qwlo[12582912]; // w_qkv
__device__ __nv_bfloat16 g_gwhi[4194304],  g_gwlo[4194304];  // w_g_proj
__device__ __nv_bfloat16 g_dwhi[4194304],  g_dwlo[4194304];  // w_dense
__device__ __nv_bfloat16 g_xhi[16777216],  g_xlo[16777216];  // gated O

__device__ __forceinline__ float head_slope(int h) {
    const float LSCALE = 0.6451712903225806f;   // 1 - 11/31 + 1e-5
    return -exp2f(-0.5f * (float)(h + 1)) * LSCALE;
}

// ---------------------------------------------------------------------------
// Packed f32x2 helpers (attention-side kernels)
// ---------------------------------------------------------------------------
__device__ __forceinline__ ull pk2(float lo, float hi) {
    ull r; asm("mov.b64 %0,{%1,%2};" : "=l"(r) : "f"(lo), "f"(hi)); return r;
}
__device__ __forceinline__ void upk2(ull v, float& lo, float& hi) {
    asm("mov.b64 {%0,%1},%2;" : "=f"(lo), "=f"(hi) : "l"(v));
}
__device__ __forceinline__ void fma2(ull& d, ull a, ull b) {
    asm("fma.rn.f32x2 %0,%1,%2,%0;" : "+l"(d) : "l"(a), "l"(b));
}

// ---------------------------------------------------------------------------
// cp.async / ldmatrix / mma primitives (arch-agnostic: sm_80+)
// ---------------------------------------------------------------------------
__device__ __forceinline__ uint32_t smem_u32(const void* p) {
    uint32_t a;
    asm("{ .reg .u64 t; cvta.to.shared.u64 t, %1; cvt.u32.u64 %0, t; }" : "=r"(a) : "l"(p));
    return a;
}
__device__ __forceinline__ void cpa16(uint32_t dst, const void* src) {
    asm volatile("cp.async.cg.shared.global [%0], [%1], 16;" :: "r"(dst), "l"(src));
}
#define CP_COMMIT() asm volatile("cp.async.commit_group;" ::: "memory")

#define LDSM4(r, a)                                                             \
    asm volatile("ldmatrix.sync.aligned.m8n8.x4.shared.b16 {%0,%1,%2,%3}, [%4];"\
        : "=r"((r)[0]), "=r"((r)[1]), "=r"((r)[2]), "=r"((r)[3]) : "r"(a))

__device__ __forceinline__ void mma16816(float* c, const uint32_t* a, const uint32_t* b) {
    asm volatile("mma.sync.aligned.m16n8k16.row.col.f32.bf16.bf16.f32 "
        "{%0,%1,%2,%3},{%4,%5,%6,%7},{%8,%9},{%0,%1,%2,%3};"
        : "+f"(c[0]), "+f"(c[1]), "+f"(c[2]), "+f"(c[3])
        : "r"(a[0]), "r"(a[1]), "r"(a[2]), "r"(a[3]), "r"(b[0]), "r"(b[1]));
}

// ---------------------------------------------------------------------------
// fp32 -> bf16 hi/lo split (4 elems/thread)
// ---------------------------------------------------------------------------
__global__ void __launch_bounds__(256) split4(
    const float* __restrict__ x, __nv_bfloat16* __restrict__ hi,
    __nv_bfloat16* __restrict__ lo, int n4)
{
    int i = blockIdx.x * 256 + threadIdx.x;
    if (i >= n4) return;
    float4 v = ((const float4*)x)[i];
    __nv_bfloat162 h01 = __floats2bfloat162_rn(v.x, v.y);
    __nv_bfloat162 h23 = __floats2bfloat162_rn(v.z, v.w);
    float r0 = v.x - __low2float(h01), r1 = v.y - __high2float(h01);
    float r2 = v.z - __low2float(h23), r3 = v.w - __high2float(h23);
    __nv_bfloat162 l01 = __floats2bfloat162_rn(r0, r1);
    __nv_bfloat162 l23 = __floats2bfloat162_rn(r2, r3);
    uint2 hp, lp;
    hp.x = *(unsigned*)&h01; hp.y = *(unsigned*)&h23;
    lp.x = *(unsigned*)&l01; lp.y = *(unsigned*)&l23;
    ((uint2*)hi)[i] = hp;
    ((uint2*)lo)[i] = lp;
}

// ---------------------------------------------------------------------------
// HMMA GEMM body (fp32-split bf16): C tile [bm..bm+128) x [bn..bn+128).
// 8 warps x (32m x 64n), K-chunk 32, 2-stage double buffer (80KB of smem).
// Per stage (40960B): Ahi@0, Alo@10240, Bhi@20480, Blo@30720; rows 64B data,
// 80B stride. Split: hi*hi + lo*hi + hi*lo.
// ---------------------------------------------------------------------------
static constexpr int STG = 40960;
template<bool SIG>
__device__ __forceinline__ void hgemm_body(
    int bx, int by, char* smem,
    const __nv_bfloat16* __restrict__ Ahi, const __nv_bfloat16* __restrict__ Alo,
    const __nv_bfloat16* __restrict__ Bhi, const __nv_bfloat16* __restrict__ Blo,
    float* __restrict__ C, int M, int N, int K)
{
    const uint32_t sb = smem_u32(smem);
    const int tid = threadIdx.x, wid = tid >> 5, lane = tid & 31;
    const int bm = by * 128, bn = bx * 128;
    const int wm = (wid & 3) * 32, wn = (wid >> 2) * 64;
    const int NC = K >> 5;

    const char* gAh = (const char*)(Ahi + (size_t)bm * K);
    const char* gAl = (const char*)(Alo + (size_t)bm * K);
    const char* gBh = (const char*)(Bhi + (size_t)bn * K);
    const char* gBl = (const char*)(Blo + (size_t)bn * K);
    const size_t grs = (size_t)K * 2;

    auto load = [&](int c, int s) {
        uint32_t stg = sb + s * STG;
        size_t ko = (size_t)c * 64;
#pragma unroll
        for (int i = 0; i < 2; i++) {
            int u = tid + 256 * i;
            int r = u >> 2; uint32_t q = (uint32_t)(u & 3) * 16;
            uint32_t so = (uint32_t)r * 80 + q;
            size_t go = (size_t)r * grs + ko + q;
            cpa16(stg + so,         gAh + go);
            cpa16(stg + 10240 + so, gAl + go);
            cpa16(stg + 20480 + so, gBh + go);
            cpa16(stg + 30720 + so, gBl + go);
        }
        CP_COMMIT();
    };

    float acc[2][8][4];
#pragma unroll
    for (int mt = 0; mt < 2; mt++)
#pragma unroll
        for (int nt = 0; nt < 8; nt++)
#pragma unroll
            for (int j = 0; j < 4; j++) acc[mt][nt][j] = 0.f;

    load(0, 0);
    load(1, 1);

    const uint32_t arow = (uint32_t)(wm + (lane & 15));
    const uint32_t brow = (uint32_t)(wn + (lane & 7) + ((lane >> 4) << 3));

    for (int c = 0; c < NC; c++) {
        if (c + 1 < NC) asm volatile("cp.async.wait_group 1;" ::: "memory");
        else            asm volatile("cp.async.wait_group 0;" ::: "memory");
        __syncthreads();
        uint32_t stg = sb + (c & 1) * STG;
#pragma unroll
        for (int s = 0; s < 2; s++) {
            uint32_t colA = (uint32_t)s * 32 + ((lane >> 4) << 4);
            uint32_t colB = (uint32_t)s * 32 + (((lane >> 3) & 1) << 4);
            uint32_t aA = stg + arow * 80 + colA;
            uint32_t aB = stg + 20480 + brow * 80 + colB;
            uint32_t ah[2][4], al[2][4], bb[4][4];
            LDSM4(ah[0], aA);
            LDSM4(ah[1], aA + 16 * 80);
#pragma unroll
            for (int p = 0; p < 4; p++) LDSM4(bb[p], aB + p * 16 * 80);
            // hi*hi
#pragma unroll
            for (int mt = 0; mt < 2; mt++)
#pragma unroll
                for (int nt = 0; nt < 8; nt++)
                    mma16816(acc[mt][nt], ah[mt], &bb[nt >> 1][(nt & 1) * 2]);
            // lo*hi
            LDSM4(al[0], aA + 10240);
            LDSM4(al[1], aA + 10240 + 16 * 80);
#pragma unroll
            for (int mt = 0; mt < 2; mt++)
#pragma unroll
                for (int nt = 0; nt < 8; nt++)
                    mma16816(acc[mt][nt], al[mt], &bb[nt >> 1][(nt & 1) * 2]);
            // hi*lo
#pragma unroll
            for (int p = 0; p < 4; p++) LDSM4(bb[p], aB + 10240 + p * 16 * 80);
#pragma unroll
            for (int mt = 0; mt < 2; mt++)
#pragma unroll
                for (int nt = 0; nt < 8; nt++)
                    mma16816(acc[mt][nt], ah[mt], &bb[nt >> 1][(nt & 1) * 2]);
        }
        __syncthreads();
        if (c + 2 < NC) load(c + 2, c & 1);
    }

    const int g = lane >> 2, tg = lane & 3;
#pragma unroll
    for (int mt = 0; mt < 2; mt++) {
        int m0 = bm + wm + mt * 16 + g;
#pragma unroll
        for (int nt = 0; nt < 8; nt++) {
            int n0 = bn + wn + nt * 8 + tg * 2;
            float v0 = acc[mt][nt][0], v1 = acc[mt][nt][1];
            float v2 = acc[mt][nt][2], v3 = acc[mt][nt][3];
            if (SIG) {
                v0 = 1.f / (1.f + expf(-v0)); v1 = 1.f / (1.f + expf(-v1));
                v2 = 1.f / (1.f + expf(-v2)); v3 = 1.f / (1.f + expf(-v3));
            }
            float2* p0 = (float2*)(C + (size_t)m0 * N + n0);
            float2* p1 = (float2*)(C + (size_t)(m0 + 8) * N + n0);
            *p0 = make_float2(v0, v1);
            *p1 = make_float2(v2, v3);
        }
    }
}

template<bool SIG>
__global__ void __launch_bounds__(256, 2) hgemm(
    const __nv_bfloat16* __restrict__ Ahi, const __nv_bfloat16* __restrict__ Alo,
    const __nv_bfloat16* __restrict__ Bhi, const __nv_bfloat16* __restrict__ Blo,
    float* __restrict__ C, int M, int N, int K)
{
    extern __shared__ char smem[];
    hgemm_body<SIG>(blockIdx.x, blockIdx.y, smem, Ahi, Alo, Bhi, Blo, C, M, N, K);
}

// ---------------------------------------------------------------------------
// gla_out body: O = (mask .* QK^T) V + diag(exp(g*(i+1))) Q S_c  for tile (c,bh)
// ---------------------------------------------------------------------------
__device__ __forceinline__ void gla_body(
    int c, int bh, char* smraw, float* __restrict__ qkv, const float* __restrict__ S)
{
    float* sm  = (float*)smraw;
    float* Qs  = sm;
    float* KVs = sm + 8448;
    float* Att = sm + 16896;
    float* St  = sm + 21248;
    int b = bh >> 4, h = bh & 15;
    float g = head_slope(h);
    int tid = threadIdx.x;

    int li = tid >> 2, lc = (tid & 3) * 32;
    const float* qrowL = qkv + (size_t)(b * 4096 + c * 64 + li) * 6144 + h * 128;
#pragma unroll
    for (int u = 0; u < 8; u++) {
        *(float4*)&Qs [li * 132 + lc + u * 4] = *(const float4*)(qrowL + lc + u * 4);
        *(float4*)&KVs[li * 132 + lc + u * 4] = *(const float4*)(qrowL + 2048 + lc + u * 4);
    }
    __syncthreads();

    int tx = tid & 15, ty = tid >> 4;
    {
        int i0 = ty * 4, j0 = tx * 4;
        float a[4][4];
#pragma unroll
        for (int ii = 0; ii < 4; ii++)
#pragma unroll
            for (int jj = 0; jj < 4; jj++) a[ii][jj] = 0.f;
        for (int d = 0; d < 128; d += 4) {
            float4 qv[4], kv4[4];
#pragma unroll
            for (int ii = 0; ii < 4; ii++) qv[ii]  = *(const float4*)&Qs [(i0 + ii) * 132 + d];
#pragma unroll
            for (int jj = 0; jj < 4; jj++) kv4[jj] = *(const float4*)&KVs[(j0 + jj) * 132 + d];
#pragma unroll
            for (int ii = 0; ii < 4; ii++)
#pragma unroll
                for (int jj = 0; jj < 4; jj++)
                    a[ii][jj] += qv[ii].x * kv4[jj].x + qv[ii].y * kv4[jj].y
                               + qv[ii].z * kv4[jj].z + qv[ii].w * kv4[jj].w;
        }
#pragma unroll
        for (int ii = 0; ii < 4; ii++)
#pragma unroll
            for (int jj = 0; jj < 4; jj++) {
                int i = i0 + ii, j = j0 + jj;
                Att[i * 68 + j] = (i >= j) ? a[ii][jj] * expf(g * (float)(i - j)) : 0.f;
            }
    }
    __syncthreads();
#pragma unroll
    for (int u = 0; u < 8; u++)
        *(float4*)&KVs[li * 132 + lc + u * 4] = *(const float4*)(qrowL + 4096 + lc + u * 4);

    int i0 = ty * 4, e0 = tx * 8;
    ull acc[4][4];
#pragma unroll
    for (int ii = 0; ii < 4; ii++)
#pragma unroll
        for (int j = 0; j < 4; j++) acc[ii][j] = 0ull;

    size_t sbase2 = (size_t)(bh * 64 + c) * 16384;
    int sr = tid >> 4, sc = (tid & 15) * 8;
    for (int dt = 0; dt < 8; dt++) {
        __syncthreads();
        *(float4*)&St[sr * 132 + sc]     = *(const float4*)(S + sbase2 + (size_t)(dt * 16 + sr) * 128 + sc);
        *(float4*)&St[sr * 132 + sc + 4] = *(const float4*)(S + sbase2 + (size_t)(dt * 16 + sr) * 128 + sc + 4);
        __syncthreads();
#pragma unroll
        for (int d = 0; d < 16; d++) {
            float4 s0 = *(const float4*)&St[d * 132 + e0];
            float4 s1 = *(const float4*)&St[d * 132 + e0 + 4];
            ull ss[4] = { pk2(s0.x, s0.y), pk2(s0.z, s0.w), pk2(s1.x, s1.y), pk2(s1.z, s1.w) };
#pragma unroll
            for (int ii = 0; ii < 4; ii++) {
                float q = Qs[(i0 + ii) * 132 + dt * 16 + d];
                ull aa = pk2(q, q);
#pragma unroll
                for (int j = 0; j < 4; j++) fma2(acc[ii][j], aa, ss[j]);
            }
        }
    }
#pragma unroll
    for (int ii = 0; ii < 4; ii++) {
        float qd = expf(g * (float)(i0 + ii + 1));
#pragma unroll
        for (int j = 0; j < 4; j++) {
            float lo, hi; upk2(acc[ii][j], lo, hi);
            acc[ii][j] = pk2(lo * qd, hi * qd);
        }
    }
#pragma unroll 4
    for (int j = 0; j < 64; j++) {
        float4 v0 = *(const float4*)&KVs[j * 132 + e0];
        float4 v1 = *(const float4*)&KVs[j * 132 + e0 + 4];
        ull vv[4] = { pk2(v0.x, v0.y), pk2(v0.z, v0.w), pk2(v1.x, v1.y), pk2(v1.z, v1.w) };
#pragma unroll
        for (int ii = 0; ii < 4; ii++) {
            float a = Att[(i0 + ii) * 68 + j];
            ull aa = pk2(a, a);
#pragma unroll
            for (int jj = 0; jj < 4; jj++) fma2(acc[ii][jj], aa, vv[jj]);
        }
    }
#pragma unroll
    for (int ii = 0; ii < 4; ii++) {
        float o[8];
#pragma unroll
        for (int j = 0; j < 4; j++) upk2(acc[ii][j], o[2 * j], o[2 * j + 1]);
        float* orow = qkv + (size_t)(b * 4096 + c * 64 + i0 + ii) * 6144 + 4096 + h * 128 + e0;
        *(float4*)orow       = make_float4(o[0], o[1], o[2], o[3]);
        *(float4*)(orow + 4) = make_float4(o[4], o[5], o[6], o[7]);
    }
}

// ---------------------------------------------------------------------------
// MERGED kernel: 3072 blocks. bid%3==2 -> gate hgemm tile (tensor pipe);
// else -> gla_out tile (fma/L1 pipes). Interleaved so both pipes co-execute.
// ---------------------------------------------------------------------------
__global__ void __launch_bounds__(256, 2) gla_gate(
    float* __restrict__ qkv, const float* __restrict__ S,
    const __nv_bfloat16* __restrict__ Ahi, const __nv_bfloat16* __restrict__ Alo,
    const __nv_bfloat16* __restrict__ Bhi, const __nv_bfloat16* __restrict__ Blo,
    float* __restrict__ gate)
{
    extern __shared__ char smem[];
    int bid = blockIdx.x;
    if (bid % 3 == 2) {
        int q = bid / 3;                        // 0..1023
        hgemm_body<true>(q & 15, q >> 4, smem, Ahi, Alo, Bhi, Blo, gate, 8192, 2048, 2048);
    } else {
        int gidx = (bid / 3) * 2 + (bid % 3);   // 0..2047
        gla_body(gidx & 63, gidx >> 6, smem, qkv, S);
    }
}

// ---------------------------------------------------------------------------
// RoPE cos/sin table (fp64 angles)
// ---------------------------------------------------------------------------
__global__ void rope_table(const int* __restrict__ pos, float* __restrict__ rope)
{
    int idx = blockIdx.x * 256 + threadIdx.x;
    int bt = idx >> 5, i = idx & 31;
    double invf = pow(10000.0, -(double)(2 * i) / 64.0);
    double ang  = (double)pos[bt] * invf;
    double sd, cd; sincos(ang, &sd, &cd);
    rope[bt * 64 + i]      = (float)cd;
    rope[bt * 64 + 32 + i] = (float)sd;
}

// ---------------------------------------------------------------------------
// Per-head RMSNorm + RoPE on q,k in place (warp per (bt,h)); q *= D^-1/2.
// ---------------------------------------------------------------------------
__global__ void __launch_bounds__(256) norm_rope(
    float* __restrict__ qkv, const float* __restrict__ qw,
    const float* __restrict__ kw, const float* __restrict__ rope)
{
    int gw   = blockIdx.x * 8 + (threadIdx.x >> 5);
    int lane = threadIdx.x & 31;
    int bt = gw >> 4, h = gw & 15;
    float* qrow = qkv + (size_t)bt * 6144 + h * 128;
    const float* rc = rope + bt * 64;

    float c4[4], s4[4];
    if (lane < 16) {
#pragma unroll
        for (int m = 0; m < 4; m++) {
            int fi = (lane * 4 + m) & 31;
            c4[m] = rc[fi]; s4[m] = rc[32 + fi];
        }
    }
    float sgn = (lane < 8) ? -1.f : 1.f;

#pragma unroll
    for (int pass = 0; pass < 2; pass++) {
        float* row = qrow + pass * 2048;
        const float* wv = pass ? kw : qw;
        float4 x = *(float4*)(row + lane * 4);
        float ss = x.x * x.x + x.y * x.y + x.z * x.z + x.w * x.w;
#pragma unroll
        for (int off = 16; off >= 1; off >>= 1) ss += __shfl_xor_sync(0xffffffffu, ss, off);
        float r = rsqrtf(ss * (1.f / 128.f) + 1e-6f);
        float4 w4 = *(const float4*)(wv + lane * 4);
        x.x *= r * w4.x; x.y *= r * w4.y; x.z *= r * w4.z; x.w *= r * w4.w;
        float px = __shfl_xor_sync(0xffffffffu, x.x, 8);
        float py = __shfl_xor_sync(0xffffffffu, x.y, 8);
        float pz = __shfl_xor_sync(0xffffffffu, x.z, 8);
        float pw = __shfl_xor_sync(0xffffffffu, x.w, 8);
        if (lane < 16) {
            x.x = x.x * c4[0] + sgn * px * s4[0];
            x.y = x.y * c4[1] + sgn * py * s4[1];
            x.z = x.z * c4[2] + sgn * pz * s4[2];
            x.w = x.w * c4[3] + sgn * pw * s4[3];
        }
        if (pass == 0) {
            const float qs = 0.08838834764831845f;
            x.x *= qs; x.y *= qs; x.z *= qs; x.w *= qs;
        }
        *(float4*)(row + lane * 4) = x;
    }
}

// ---------------------------------------------------------------------------
// Per-chunk decayed KV outer product (f32x2)
// ---------------------------------------------------------------------------
__global__ void __launch_bounds__(256) kv_outer(
    const float* __restrict__ qkv, float* __restrict__ kv)
{
    extern __shared__ __align__(16) float sm[];
    float* Ks = sm;
    float* Vs = sm + 64 * 132;
    int c = blockIdx.x, bh = blockIdx.y;
    int b = bh >> 4, h = bh & 15;
    float g = head_slope(h);
    int tid = threadIdx.x;

    int li = tid >> 2, lc = (tid & 3) * 32;
    const float* krow = qkv + (size_t)(b * 4096 + c * 64 + li) * 6144 + 2048 + h * 128;
    float kd = expf(g * (float)(63 - li));
#pragma unroll
    for (int u = 0; u < 8; u++) {
        float4 kk = *(const float4*)(krow + lc + u * 4);
        kk.x *= kd; kk.y *= kd; kk.z *= kd; kk.w *= kd;
        *(float4*)&Ks[li * 132 + lc + u * 4] = kk;
        *(float4*)&Vs[li * 132 + lc + u * 4] = *(const float4*)(krow + 2048 + lc + u * 4);
    }
    __syncthreads();

    int tx = tid & 15, ty = tid >> 4;
    int d0 = ty * 8, e0 = tx * 8;
    ull acc[8][4];
#pragma unroll
    for (int i = 0; i < 8; i++)
#pragma unroll
        for (int j = 0; j < 4; j++) acc[i][j] = 0ull;

    for (int i = 0; i < 64; i++) {
        float4 k0 = *(const float4*)&Ks[i * 132 + d0];
        float4 k1 = *(const float4*)&Ks[i * 132 + d0 + 4];
        float4 v0 = *(const float4*)&Vs[i * 132 + e0];
        float4 v1 = *(const float4*)&Vs[i * 132 + e0 + 4];
        ull vv[4] = { pk2(v0.x, v0.y), pk2(v0.z, v0.w), pk2(v1.x, v1.y), pk2(v1.z, v1.w) };
        float km[8] = { k0.x, k0.y, k0.z, k0.w, k1.x, k1.y, k1.z, k1.w };
#pragma unroll
        for (int di = 0; di < 8; di++) {
            ull aa = pk2(km[di], km[di]);
#pragma unroll
            for (int j = 0; j < 4; j++) fma2(acc[di][j], aa, vv[j]);
        }
    }
    size_t base = (size_t)(bh * 64 + c) * 16384;
#pragma unroll
    for (int di = 0; di < 8; di++) {
        float o[8];
#pragma unroll
        for (int j = 0; j < 4; j++) upk2(acc[di][j], o[2 * j], o[2 * j + 1]);
        float* op = kv + base + (size_t)(d0 + di) * 128 + e0;
        *(float4*)op       = make_float4(o[0], o[1], o[2], o[3]);
        *(float4*)(op + 4) = make_float4(o[4], o[5], o[6], o[7]);
    }
}

// ---------------------------------------------------------------------------
// In-place decay scan over kv: writes pre-state S_c
// ---------------------------------------------------------------------------
__global__ void __launch_bounds__(256) scan_states(float* __restrict__ kv)
{
    int t  = blockIdx.x * 256 + threadIdx.x;
    int bh = t >> 14, de = t & 16383;
    float dec = expf(head_slope(bh & 15) * 64.f);
    size_t base = (size_t)bh * 64 * 16384 + de;
    float st = 0.f;
#pragma unroll 1
    for (int c = 0; c < 64; c++) {
        float kvv = kv[base + (size_t)c * 16384];
        kv[base + (size_t)c * 16384] = st;
        st = dec * st + kvv;
    }
}

// ---------------------------------------------------------------------------
// Group RMSNorm * g_norm_w * sigmoid-gate -> bf16 hi/lo split (fused)
// ---------------------------------------------------------------------------
__global__ void __launch_bounds__(256) gate_norm(
    const float* __restrict__ qkv, const float* __restrict__ gate,
    const float* __restrict__ gw,
    __nv_bfloat16* __restrict__ xhi, __nv_bfloat16* __restrict__ xlo)
{
    int gwid = blockIdx.x * 8 + (threadIdx.x >> 5);
    int lane = threadIdx.x & 31;
    int bt = gwid >> 4, h = gwid & 15;
    const float* orow = qkv + (size_t)bt * 6144 + 4096 + h * 128;
    float4 x = *(const float4*)(orow + lane * 4);
    float ss = x.x * x.x + x.y * x.y + x.z * x.z + x.w * x.w;
#pragma unroll
    for (int off = 16; off >= 1; off >>= 1) ss += __shfl_xor_sync(0xffffffffu, ss, off);
    float r = rsqrtf(ss * (1.f / 128.f) + 1e-6f);
    float4 w  = *(const float4*)(gw + h * 128 + lane * 4);
    size_t idx = (size_t)bt * 2048 + h * 128 + lane * 4;
    float4 gt = *(const float4*)(gate + idx);
    float4 o;
    o.x = x.x * r * w.x * gt.x;
    o.y = x.y * r * w.y * gt.y;
    o.z = x.z * r * w.z * gt.z;
    o.w = x.w * r * w.w * gt.w;
    __nv_bfloat162 h01 = __floats2bfloat162_rn(o.x, o.y);
    __nv_bfloat162 h23 = __floats2bfloat162_rn(o.z, o.w);
    float r0 = o.x - __low2float(h01), r1 = o.y - __high2float(h01);
    float r2 = o.z - __low2float(h23), r3 = o.w - __high2float(h23);
    __nv_bfloat162 l01 = __floats2bfloat162_rn(r0, r1);
    __nv_bfloat162 l23 = __floats2bfloat162_rn(r2, r3);
    uint2 hp, lp;
    hp.x = *(unsigned*)&h01; hp.y = *(unsigned*)&h23;
    lp.x = *(unsigned*)&l01; lp.y = *(unsigned*)&l23;
    *(uint2*)(xhi + idx) = hp;
    *(uint2*)(xlo + idx) = lp;
}

// ---------------------------------------------------------------------------
extern "C" void kernel_launch(void* const* d_in, const int* in_sizes, int n_in,
                              void* d_out, int out_size)
{
    const float* hidden   = (const float*)d_in[0];
    const float* w_qkv    = (const float*)d_in[1];
    const float* q_ln_w   = (const float*)d_in[2];
    const float* k_ln_w   = (const float*)d_in[3];
    const float* g_norm_w = (const float*)d_in[4];
    const float* w_g_proj = (const float*)d_in[5];
    const float* w_dense  = (const float*)d_in[6];
    const int*   pos_ids  = (const int*)d_in[7];
    float* out = (float*)d_out;
    (void)in_sizes; (void)n_in; (void)out_size;

    float *qkv, *gate, *kv, *rope;
    cudaGetSymbolAddress((void**)&qkv,  g_qkv);
    cudaGetSymbolAddress((void**)&gate, g_gate);
    cudaGetSymbolAddress((void**)&kv,   g_kv);
    cudaGetSymbolAddress((void**)&rope, g_rope);
    __nv_bfloat16 *hhi, *hlo, *qwhi, *qwlo, *gwhi, *gwlo, *dwhi, *dwlo, *xhi, *xlo;
    cudaGetSymbolAddress((void**)&hhi,  g_hhi);  cudaGetSymbolAddress((void**)&hlo,  g_hlo);
    cudaGetSymbolAddress((void**)&qwhi, g_qwhi); cudaGetSymbolAddress((void**)&qwlo, g_qwlo);
    cudaGetSymbolAddress((void**)&gwhi, g_gwhi); cudaGetSymbolAddress((void**)&gwlo, g_gwlo);
    cudaGetSymbolAddress((void**)&dwhi, g_dwhi); cudaGetSymbolAddress((void**)&dwlo, g_dwlo);
    cudaGetSymbolAddress((void**)&xhi,  g_xhi);  cudaGetSymbolAddress((void**)&xlo,  g_xlo);

    cudaFuncSetAttribute(kv_outer, cudaFuncAttributeMaxDynamicSharedMemorySize, 67584);
    cudaFuncSetAttribute(gla_gate, cudaFuncAttributeMaxDynamicSharedMemorySize, 93440);
    cudaFuncSetAttribute(hgemm<false>, cudaFuncAttributeMaxDynamicSharedMemorySize, 2 * STG);
    cudaFuncSetAttribute(hgemm<true>,  cudaFuncAttributeMaxDynamicSharedMemorySize, 2 * STG);

    rope_table<<<1024, 256>>>(pos_ids, rope);
    split4<<<16384, 256>>>(hidden,   hhi,  hlo,  4194304);
    split4<<<12288, 256>>>(w_qkv,    qwhi, qwlo, 3145728);
    split4<<< 4096, 256>>>(w_g_proj, gwhi, gwlo, 1048576);
    split4<<< 4096, 256>>>(w_dense,  dwhi, dwlo, 1048576);

    hgemm<false><<<dim3(48, 64), 256, 2 * STG>>>(hhi, hlo, qwhi, qwlo, qkv, 8192, 6144, 2048);
    norm_rope<<<16384, 256>>>(qkv, q_ln_w, k_ln_w, rope);
    kv_outer<<<dim3(64, 32), 256, 67584>>>(qkv, kv);
    scan_states<<<2048, 256>>>(kv);
    // merged: gla_out tiles + gate hgemm tiles in one heterogeneous launch
    gla_gate<<<3072, 256, 93440>>>(qkv, kv, hhi, hlo, gwhi, gwlo, gate);
    gate_norm<<<16384, 256>>>(qkv, gate, g_norm_w, xhi, xlo);
    hgemm<false><<<dim3(16, 64), 256, 2 * STG>>>(xhi, xlo, dwhi, dwlo, out, 8192, 2048, 2048);
}

// round 15
// speedup vs baseline: 1.2324x; 1.1184x over previous
#include <cuda_runtime.h>
#include <cuda_bf16.h>
#include <cuda_fp16.h>
#include <math.h>
#include <stdint.h>

// B=2, T=4096, HID=2048, H=16, D=128, ROPE_DIM=64, CHUNK=64, nc=64
typedef unsigned long long ull;

// ---------------------------------------------------------------------------
// Scratch (device globals; allocation is forbidden)
// ---------------------------------------------------------------------------
__device__ float g_qkv [50331648];  // [8192][6144]  q|k|v
__device__ float g_gate[16777216];  // [8192][2048]  sigmoid(gate)
__device__ float g_kv  [33554432];  // [B*H*64][128][128] chunk KV -> in-place S_c
__device__ float g_rope[  524288];  // [8192][64] cos|sin

// 16-bit split buffers (fp16 bits for QKV/gate path, bf16 bits for dense path)
__device__ __nv_bfloat16 g_hhi[16777216], g_hlo[16777216];   // hidden (fp16)
__device__ __nv_bfloat16 g_qwhi[12582912], g_qwlo[12582912]; // w_qkv (fp16)
__device__ __nv_bfloat16 g_gwhi[4194304],  g_gwlo[4194304];  // w_g_proj (fp16)
__device__ __nv_bfloat16 g_dwhi[4194304],  g_dwlo[4194304];  // w_dense (bf16)
__device__ __nv_bfloat16 g_xhi[16777216],  g_xlo[16777216];  // gated O (bf16)

__device__ __forceinline__ float head_slope(int h) {
    const float LSCALE = 0.6451712903225806f;   // 1 - 11/31 + 1e-5
    return -exp2f(-0.5f * (float)(h + 1)) * LSCALE;
}

// ---------------------------------------------------------------------------
// Packed f32x2 helpers (attention-side kernels)
// ---------------------------------------------------------------------------
__device__ __forceinline__ ull pk2(float lo, float hi) {
    ull r; asm("mov.b64 %0,{%1,%2};" : "=l"(r) : "f"(lo), "f"(hi)); return r;
}
__device__ __forceinline__ void upk2(ull v, float& lo, float& hi) {
    asm("mov.b64 {%0,%1},%2;" : "=f"(lo), "=f"(hi) : "l"(v));
}
__device__ __forceinline__ void fma2(ull& d, ull a, ull b) {
    asm("fma.rn.f32x2 %0,%1,%2,%0;" : "+l"(d) : "l"(a), "l"(b));
}

// ---------------------------------------------------------------------------
// cp.async / ldmatrix / mma primitives (arch-agnostic: sm_80+)
// ---------------------------------------------------------------------------
__device__ __forceinline__ uint32_t smem_u32(const void* p) {
    uint32_t a;
    asm("{ .reg .u64 t; cvta.to.shared.u64 t, %1; cvt.u32.u64 %0, t; }" : "=r"(a) : "l"(p));
    return a;
}
__device__ __forceinline__ void cpa16(uint32_t dst, const void* src) {
    asm volatile("cp.async.cg.shared.global [%0], [%1], 16;" :: "r"(dst), "l"(src));
}
#define CP_COMMIT() asm volatile("cp.async.commit_group;" ::: "memory")

#define LDSM4(r, a)                                                             \
    asm volatile("ldmatrix.sync.aligned.m8n8.x4.shared.b16 {%0,%1,%2,%3}, [%4];"\
        : "=r"((r)[0]), "=r"((r)[1]), "=r"((r)[2]), "=r"((r)[3]) : "r"(a))

__device__ __forceinline__ void mma16816(float* c, const uint32_t* a, const uint32_t* b) {
    asm volatile("mma.sync.aligned.m16n8k16.row.col.f32.bf16.bf16.f32 "
        "{%0,%1,%2,%3},{%4,%5,%6,%7},{%8,%9},{%0,%1,%2,%3};"
        : "+f"(c[0]), "+f"(c[1]), "+f"(c[2]), "+f"(c[3])
        : "r"(a[0]), "r"(a[1]), "r"(a[2]), "r"(a[3]), "r"(b[0]), "r"(b[1]));
}
__device__ __forceinline__ void mma16816f(float* c, const uint32_t* a, const uint32_t* b) {
    asm volatile("mma.sync.aligned.m16n8k16.row.col.f32.f16.f16.f32 "
        "{%0,%1,%2,%3},{%4,%5,%6,%7},{%8,%9},{%0,%1,%2,%3};"
        : "+f"(c[0]), "+f"(c[1]), "+f"(c[2]), "+f"(c[3])
        : "r"(a[0]), "r"(a[1]), "r"(a[2]), "r"(a[3]), "r"(b[0]), "r"(b[1]));
}

// ---------------------------------------------------------------------------
// fp32 -> bf16 hi/lo split (4 elems/thread)
// ---------------------------------------------------------------------------
__global__ void __launch_bounds__(256) split4(
    const float* __restrict__ x, __nv_bfloat16* __restrict__ hi,
    __nv_bfloat16* __restrict__ lo, int n4)
{
    int i = blockIdx.x * 256 + threadIdx.x;
    if (i >= n4) return;
    float4 v = ((const float4*)x)[i];
    __nv_bfloat162 h01 = __floats2bfloat162_rn(v.x, v.y);
    __nv_bfloat162 h23 = __floats2bfloat162_rn(v.z, v.w);
    float r0 = v.x - __low2float(h01), r1 = v.y - __high2float(h01);
    float r2 = v.z - __low2float(h23), r3 = v.w - __high2float(h23);
    __nv_bfloat162 l01 = __floats2bfloat162_rn(r0, r1);
    __nv_bfloat162 l23 = __floats2bfloat162_rn(r2, r3);
    uint2 hp, lp;
    hp.x = *(unsigned*)&h01; hp.y = *(unsigned*)&h23;
    lp.x = *(unsigned*)&l01; lp.y = *(unsigned*)&l23;
    ((uint2*)hi)[i] = hp;
    ((uint2*)lo)[i] = lp;
}

// ---------------------------------------------------------------------------
// fp32 -> fp16 hi/lo split (4 elems/thread); bits stored in bf16 arrays
// ---------------------------------------------------------------------------
__global__ void __launch_bounds__(256) split4h(
    const float* __restrict__ x, __nv_bfloat16* __restrict__ hi_,
    __nv_bfloat16* __restrict__ lo_, int n4)
{
    int i = blockIdx.x * 256 + threadIdx.x;
    if (i >= n4) return;
    float4 v = ((const float4*)x)[i];
    __half2 h01 = __floats2half2_rn(v.x, v.y);
    __half2 h23 = __floats2half2_rn(v.z, v.w);
    float r0 = v.x - __low2float(h01), r1 = v.y - __high2float(h01);
    float r2 = v.z - __low2float(h23), r3 = v.w - __high2float(h23);
    __half2 l01 = __floats2half2_rn(r0, r1);
    __half2 l23 = __floats2half2_rn(r2, r3);
    uint2 hp, lp;
    hp.x = *(unsigned*)&h01; hp.y = *(unsigned*)&h23;
    lp.x = *(unsigned*)&l01; lp.y = *(unsigned*)&l23;
    ((uint2*)hi_)[i] = hp;
    ((uint2*)lo_)[i] = lp;
}

// ---------------------------------------------------------------------------
// HMMA GEMM body: C tile [bm..bm+128) x [bn..bn+128).
// 8 warps x (32m x 64n), K-chunk 32, 2-stage double buffer (80KB smem).
// Per stage (40960B): Ahi@0, Alo@10240, Bhi@20480, Blo@30720; rows 64B data,
// 80B stride. F16: fp16 mma; TERMS=3: hi*hi + lo*hi + hi*lo, TERMS=2 drops hi*lo.
// ---------------------------------------------------------------------------
static constexpr int STG = 40960;
template<bool SIG, bool F16, int TERMS>
__device__ __forceinline__ void hgemm_body(
    int bx, int by, char* smem,
    const __nv_bfloat16* __restrict__ Ahi, const __nv_bfloat16* __restrict__ Alo,
    const __nv_bfloat16* __restrict__ Bhi, const __nv_bfloat16* __restrict__ Blo,
    float* __restrict__ C, int M, int N, int K)
{
    const uint32_t sb = smem_u32(smem);
    const int tid = threadIdx.x, wid = tid >> 5, lane = tid & 31;
    const int bm = by * 128, bn = bx * 128;
    const int wm = (wid & 3) * 32, wn = (wid >> 2) * 64;
    const int NC = K >> 5;

    const char* gAh = (const char*)(Ahi + (size_t)bm * K);
    const char* gAl = (const char*)(Alo + (size_t)bm * K);
    const char* gBh = (const char*)(Bhi + (size_t)bn * K);
    const char* gBl = (const char*)(Blo + (size_t)bn * K);
    const size_t grs = (size_t)K * 2;

    auto load = [&](int c, int s) {
        uint32_t stg = sb + s * STG;
        size_t ko = (size_t)c * 64;
#pragma unroll
        for (int i = 0; i < 2; i++) {
            int u = tid + 256 * i;
            int r = u >> 2; uint32_t q = (uint32_t)(u & 3) * 16;
            uint32_t so = (uint32_t)r * 80 + q;
            size_t go = (size_t)r * grs + ko + q;
            cpa16(stg + so,         gAh + go);
            cpa16(stg + 10240 + so, gAl + go);
            cpa16(stg + 20480 + so, gBh + go);
            if (TERMS == 3) cpa16(stg + 30720 + so, gBl + go);
        }
        CP_COMMIT();
    };

    float acc[2][8][4];
#pragma unroll
    for (int mt = 0; mt < 2; mt++)
#pragma unroll
        for (int nt = 0; nt < 8; nt++)
#pragma unroll
            for (int j = 0; j < 4; j++) acc[mt][nt][j] = 0.f;

    load(0, 0);
    load(1, 1);

    const uint32_t arow = (uint32_t)(wm + (lane & 15));
    const uint32_t brow = (uint32_t)(wn + (lane & 7) + ((lane >> 4) << 3));

    for (int c = 0; c < NC; c++) {
        if (c + 1 < NC) asm volatile("cp.async.wait_group 1;" ::: "memory");
        else            asm volatile("cp.async.wait_group 0;" ::: "memory");
        __syncthreads();
        uint32_t stg = sb + (c & 1) * STG;
#pragma unroll
        for (int s = 0; s < 2; s++) {
            uint32_t colA = (uint32_t)s * 32 + ((lane >> 4) << 4);
            uint32_t colB = (uint32_t)s * 32 + (((lane >> 3) & 1) << 4);
            uint32_t aA = stg + arow * 80 + colA;
            uint32_t aB = stg + 20480 + brow * 80 + colB;
            uint32_t ah[2][4], al[2][4], bb[4][4];
            LDSM4(ah[0], aA);
            LDSM4(ah[1], aA + 16 * 80);
#pragma unroll
            for (int p = 0; p < 4; p++) LDSM4(bb[p], aB + p * 16 * 80);
            // hi*hi
#pragma unroll
            for (int mt = 0; mt < 2; mt++)
#pragma unroll
                for (int nt = 0; nt < 8; nt++) {
                    if (F16) mma16816f(acc[mt][nt], ah[mt], &bb[nt >> 1][(nt & 1) * 2]);
                    else     mma16816 (acc[mt][nt], ah[mt], &bb[nt >> 1][(nt & 1) * 2]);
                }
            // lo*hi
            LDSM4(al[0], aA + 10240);
            LDSM4(al[1], aA + 10240 + 16 * 80);
#pragma unroll
            for (int mt = 0; mt < 2; mt++)
#pragma unroll
                for (int nt = 0; nt < 8; nt++) {
                    if (F16) mma16816f(acc[mt][nt], al[mt], &bb[nt >> 1][(nt & 1) * 2]);
                    else     mma16816 (acc[mt][nt], al[mt], &bb[nt >> 1][(nt & 1) * 2]);
                }
            // hi*lo (3-term only)
            if (TERMS == 3) {
#pragma unroll
                for (int p = 0; p < 4; p++) LDSM4(bb[p], aB + 10240 + p * 16 * 80);
#pragma unroll
                for (int mt = 0; mt < 2; mt++)
#pragma unroll
                    for (int nt = 0; nt < 8; nt++) {
                        if (F16) mma16816f(acc[mt][nt], ah[mt], &bb[nt >> 1][(nt & 1) * 2]);
                        else     mma16816 (acc[mt][nt], ah[mt], &bb[nt >> 1][(nt & 1) * 2]);
                    }
            }
        }
        __syncthreads();
        if (c + 2 < NC) load(c + 2, c & 1);
    }

    const int g = lane >> 2, tg = lane & 3;
#pragma unroll
    for (int mt = 0; mt < 2; mt++) {
        int m0 = bm + wm + mt * 16 + g;
#pragma unroll
        for (int nt = 0; nt < 8; nt++) {
            int n0 = bn + wn + nt * 8 + tg * 2;
            float v0 = acc[mt][nt][0], v1 = acc[mt][nt][1];
            float v2 = acc[mt][nt][2], v3 = acc[mt][nt][3];
            if (SIG) {
                v0 = 1.f / (1.f + expf(-v0)); v1 = 1.f / (1.f + expf(-v1));
                v2 = 1.f / (1.f + expf(-v2)); v3 = 1.f / (1.f + expf(-v3));
            }
            float2* p0 = (float2*)(C + (size_t)m0 * N + n0);
            float2* p1 = (float2*)(C + (size_t)(m0 + 8) * N + n0);
            *p0 = make_float2(v0, v1);
            *p1 = make_float2(v2, v3);
        }
    }
}

template<bool SIG, bool F16, int TERMS>
__global__ void __launch_bounds__(256, 2) hgemm(
    const __nv_bfloat16* __restrict__ Ahi, const __nv_bfloat16* __restrict__ Alo,
    const __nv_bfloat16* __restrict__ Bhi, const __nv_bfloat16* __restrict__ Blo,
    float* __restrict__ C, int M, int N, int K)
{
    extern __shared__ char smem[];
    hgemm_body<SIG, F16, TERMS>(blockIdx.x, blockIdx.y, smem, Ahi, Alo, Bhi, Blo, C, M, N, K);
}

// ---------------------------------------------------------------------------
// gla_out body: O = (mask .* QK^T) V + diag(exp(g*(i+1))) Q S_c  for tile (c,bh)
// ---------------------------------------------------------------------------
__device__ __forceinline__ void gla_body(
    int c, int bh, char* smraw, float* __restrict__ qkv, const float* __restrict__ S)
{
    float* sm  = (float*)smraw;
    float* Qs  = sm;
    float* KVs = sm + 8448;
    float* Att = sm + 16896;
    float* St  = sm + 21248;
    int b = bh >> 4, h = bh & 15;
    float g = head_slope(h);
    int tid = threadIdx.x;

    int li = tid >> 2, lc = (tid & 3) * 32;
    const float* qrowL = qkv + (size_t)(b * 4096 + c * 64 + li) * 6144 + h * 128;
#pragma unroll
    for (int u = 0; u < 8; u++) {
        *(float4*)&Qs [li * 132 + lc + u * 4] = *(const float4*)(qrowL + lc + u * 4);
        *(float4*)&KVs[li * 132 + lc + u * 4] = *(const float4*)(qrowL + 2048 + lc + u * 4);
    }
    __syncthreads();

    int tx = tid & 15, ty = tid >> 4;
    {
        int i0 = ty * 4, j0 = tx * 4;
        float a[4][4];
#pragma unroll
        for (int ii = 0; ii < 4; ii++)
#pragma unroll
            for (int jj = 0; jj < 4; jj++) a[ii][jj] = 0.f;
        for (int d = 0; d < 128; d += 4) {
            float4 qv[4], kv4[4];
#pragma unroll
            for (int ii = 0; ii < 4; ii++) qv[ii]  = *(const float4*)&Qs [(i0 + ii) * 132 + d];
#pragma unroll
            for (int jj = 0; jj < 4; jj++) kv4[jj] = *(const float4*)&KVs[(j0 + jj) * 132 + d];
#pragma unroll
            for (int ii = 0; ii < 4; ii++)
#pragma unroll
                for (int jj = 0; jj < 4; jj++)
                    a[ii][jj] += qv[ii].x * kv4[jj].x + qv[ii].y * kv4[jj].y
                               + qv[ii].z * kv4[jj].z + qv[ii].w * kv4[jj].w;
        }
#pragma unroll
        for (int ii = 0; ii < 4; ii++)
#pragma unroll
            for (int jj = 0; jj < 4; jj++) {
                int i = i0 + ii, j = j0 + jj;
                Att[i * 68 + j] = (i >= j) ? a[ii][jj] * expf(g * (float)(i - j)) : 0.f;
            }
    }
    __syncthreads();
#pragma unroll
    for (int u = 0; u < 8; u++)
        *(float4*)&KVs[li * 132 + lc + u * 4] = *(const float4*)(qrowL + 4096 + lc + u * 4);

    int i0 = ty * 4, e0 = tx * 8;
    ull acc[4][4];
#pragma unroll
    for (int ii = 0; ii < 4; ii++)
#pragma unroll
        for (int j = 0; j < 4; j++) acc[ii][j] = 0ull;

    size_t sbase2 = (size_t)(bh * 64 + c) * 16384;
    int sr = tid >> 4, sc = (tid & 15) * 8;
    for (int dt = 0; dt < 8; dt++) {
        __syncthreads();
        *(float4*)&St[sr * 132 + sc]     = *(const float4*)(S + sbase2 + (size_t)(dt * 16 + sr) * 128 + sc);
        *(float4*)&St[sr * 132 + sc + 4] = *(const float4*)(S + sbase2 + (size_t)(dt * 16 + sr) * 128 + sc + 4);
        __syncthreads();
#pragma unroll
        for (int d = 0; d < 16; d++) {
            float4 s0 = *(const float4*)&St[d * 132 + e0];
            float4 s1 = *(const float4*)&St[d * 132 + e0 + 4];
            ull ss[4] = { pk2(s0.x, s0.y), pk2(s0.z, s0.w), pk2(s1.x, s1.y), pk2(s1.z, s1.w) };
#pragma unroll
            for (int ii = 0; ii < 4; ii++) {
                float q = Qs[(i0 + ii) * 132 + dt * 16 + d];
                ull aa = pk2(q, q);
#pragma unroll
                for (int j = 0; j < 4; j++) fma2(acc[ii][j], aa, ss[j]);
            }
        }
    }
#pragma unroll
    for (int ii = 0; ii < 4; ii++) {
        float qd = expf(g * (float)(i0 + ii + 1));
#pragma unroll
        for (int j = 0; j < 4; j++) {
            float lo, hi; upk2(acc[ii][j], lo, hi);
            acc[ii][j] = pk2(lo * qd, hi * qd);
        }
    }
#pragma unroll 4
    for (int j = 0; j < 64; j++) {
        float4 v0 = *(const float4*)&KVs[j * 132 + e0];
        float4 v1 = *(const float4*)&KVs[j * 132 + e0 + 4];
        ull vv[4] = { pk2(v0.x, v0.y), pk2(v0.z, v0.w), pk2(v1.x, v1.y), pk2(v1.z, v1.w) };
#pragma unroll
        for (int ii = 0; ii < 4; ii++) {
            float a = Att[(i0 + ii) * 68 + j];
            ull aa = pk2(a, a);
#pragma unroll
            for (int jj = 0; jj < 4; jj++) fma2(acc[ii][jj], aa, vv[jj]);
        }
    }
#pragma unroll
    for (int ii = 0; ii < 4; ii++) {
        float o[8];
#pragma unroll
        for (int j = 0; j < 4; j++) upk2(acc[ii][j], o[2 * j], o[2 * j + 1]);
        float* orow = qkv + (size_t)(b * 4096 + c * 64 + i0 + ii) * 6144 + 4096 + h * 128 + e0;
        *(float4*)orow       = make_float4(o[0], o[1], o[2], o[3]);
        *(float4*)(orow + 4) = make_float4(o[4], o[5], o[6], o[7]);
    }
}

// ---------------------------------------------------------------------------
// MERGED kernel: 3072 blocks. bid%3==2 -> gate hgemm tile (tensor pipe, fp16
// 2-term); else -> gla_out tile (fma/L1 pipes).
// ---------------------------------------------------------------------------
__global__ void __launch_bounds__(256, 2) gla_gate(
    float* __restrict__ qkv, const float* __restrict__ S,
    const __nv_bfloat16* __restrict__ Ahi, const __nv_bfloat16* __restrict__ Alo,
    const __nv_bfloat16* __restrict__ Bhi, const __nv_bfloat16* __restrict__ Blo,
    float* __restrict__ gate)
{
    extern __shared__ char smem[];
    int bid = blockIdx.x;
    if (bid % 3 == 2) {
        int q = bid / 3;                        // 0..1023
        hgemm_body<true, true, 2>(q & 15, q >> 4, smem, Ahi, Alo, Bhi, Blo, gate, 8192, 2048, 2048);
    } else {
        int gidx = (bid / 3) * 2 + (bid % 3);   // 0..2047
        gla_body(gidx & 63, gidx >> 6, smem, qkv, S);
    }
}

// ---------------------------------------------------------------------------
// RoPE cos/sin table (fp64 angles)
// ---------------------------------------------------------------------------
__global__ void rope_table(const int* __restrict__ pos, float* __restrict__ rope)
{
    int idx = blockIdx.x * 256 + threadIdx.x;
    int bt = idx >> 5, i = idx & 31;
    double invf = pow(10000.0, -(double)(2 * i) / 64.0);
    double ang  = (double)pos[bt] * invf;
    double sd, cd; sincos(ang, &sd, &cd);
    rope[bt * 64 + i]      = (float)cd;
    rope[bt * 64 + 32 + i] = (float)sd;
}

// ---------------------------------------------------------------------------
// Per-head RMSNorm + RoPE on q,k in place (warp per (bt,h)); q *= D^-1/2.
// ---------------------------------------------------------------------------
__global__ void __launch_bounds__(256) norm_rope(
    float* __restrict__ qkv, const float* __restrict__ qw,
    const float* __restrict__ kw, const float* __restrict__ rope)
{
    int gw   = blockIdx.x * 8 + (threadIdx.x >> 5);
    int lane = threadIdx.x & 31;
    int bt = gw >> 4, h = gw & 15;
    float* qrow = qkv + (size_t)bt * 6144 + h * 128;
    const float* rc = rope + bt * 64;

    float c4[4], s4[4];
    if (lane < 16) {
#pragma unroll
        for (int m = 0; m < 4; m++) {
            int fi = (lane * 4 + m) & 31;
            c4[m] = rc[fi]; s4[m] = rc[32 + fi];
        }
    }
    float sgn = (lane < 8) ? -1.f : 1.f;

#pragma unroll
    for (int pass = 0; pass < 2; pass++) {
        float* row = qrow + pass * 2048;
        const float* wv = pass ? kw : qw;
        float4 x = *(float4*)(row + lane * 4);
        float ss = x.x * x.x + x.y * x.y + x.z * x.z + x.w * x.w;
#pragma unroll
        for (int off = 16; off >= 1; off >>= 1) ss += __shfl_xor_sync(0xffffffffu, ss, off);
        float r = rsqrtf(ss * (1.f / 128.f) + 1e-6f);
        float4 w4 = *(const float4*)(wv + lane * 4);
        x.x *= r * w4.x; x.y *= r * w4.y; x.z *= r * w4.z; x.w *= r * w4.w;
        float px = __shfl_xor_sync(0xffffffffu, x.x, 8);
        float py = __shfl_xor_sync(0xffffffffu, x.y, 8);
        float pz = __shfl_xor_sync(0xffffffffu, x.z, 8);
        float pw = __shfl_xor_sync(0xffffffffu, x.w, 8);
        if (lane < 16) {
            x.x = x.x * c4[0] + sgn * px * s4[0];
            x.y = x.y * c4[1] + sgn * py * s4[1];
            x.z = x.z * c4[2] + sgn * pz * s4[2];
            x.w = x.w * c4[3] + sgn * pw * s4[3];
        }
        if (pass == 0) {
            const float qs = 0.08838834764831845f;
            x.x *= qs; x.y *= qs; x.z *= qs; x.w *= qs;
        }
        *(float4*)(row + lane * 4) = x;
    }
}

// ---------------------------------------------------------------------------
// Per-chunk decayed KV outer product (f32x2)
// ---------------------------------------------------------------------------
__global__ void __launch_bounds__(256) kv_outer(
    const float* __restrict__ qkv, float* __restrict__ kv)
{
    extern __shared__ __align__(16) float sm[];
    float* Ks = sm;
    float* Vs = sm + 64 * 132;
    int c = blockIdx.x, bh = blockIdx.y;
    int b = bh >> 4, h = bh & 15;
    float g = head_slope(h);
    int tid = threadIdx.x;

    int li = tid >> 2, lc = (tid & 3) * 32;
    const float* krow = qkv + (size_t)(b * 4096 + c * 64 + li) * 6144 + 2048 + h * 128;
    float kd = expf(g * (float)(63 - li));
#pragma unroll
    for (int u = 0; u < 8; u++) {
        float4 kk = *(const float4*)(krow + lc + u * 4);
        kk.x *= kd; kk.y *= kd; kk.z *= kd; kk.w *= kd;
        *(float4*)&Ks[li * 132 + lc + u * 4] = kk;
        *(float4*)&Vs[li * 132 + lc + u * 4] = *(const float4*)(krow + 2048 + lc + u * 4);
    }
    __syncthreads();

    int tx = tid & 15, ty = tid >> 4;
    int d0 = ty * 8, e0 = tx * 8;
    ull acc[8][4];
#pragma unroll
    for (int i = 0; i < 8; i++)
#pragma unroll
        for (int j = 0; j < 4; j++) acc[i][j] = 0ull;

    for (int i = 0; i < 64; i++) {
        float4 k0 = *(const float4*)&Ks[i * 132 + d0];
        float4 k1 = *(const float4*)&Ks[i * 132 + d0 + 4];
        float4 v0 = *(const float4*)&Vs[i * 132 + e0];
        float4 v1 = *(const float4*)&Vs[i * 132 + e0 + 4];
        ull vv[4] = { pk2(v0.x, v0.y), pk2(v0.z, v0.w), pk2(v1.x, v1.y), pk2(v1.z, v1.w) };
        float km[8] = { k0.x, k0.y, k0.z, k0.w, k1.x, k1.y, k1.z, k1.w };
#pragma unroll
        for (int di = 0; di < 8; di++) {
            ull aa = pk2(km[di], km[di]);
#pragma unroll
            for (int j = 0; j < 4; j++) fma2(acc[di][j], aa, vv[j]);
        }
    }
    size_t base = (size_t)(bh * 64 + c) * 16384;
#pragma unroll
    for (int di = 0; di < 8; di++) {
        float o[8];
#pragma unroll
        for (int j = 0; j < 4; j++) upk2(acc[di][j], o[2 * j], o[2 * j + 1]);
        float* op = kv + base + (size_t)(d0 + di) * 128 + e0;
        *(float4*)op       = make_float4(o[0], o[1], o[2], o[3]);
        *(float4*)(op + 4) = make_float4(o[4], o[5], o[6], o[7]);
    }
}

// ---------------------------------------------------------------------------
// In-place decay scan over kv: writes pre-state S_c
// ---------------------------------------------------------------------------
__global__ void __launch_bounds__(256) scan_states(float* __restrict__ kv)
{
    int t  = blockIdx.x * 256 + threadIdx.x;
    int bh = t >> 14, de = t & 16383;
    float dec = expf(head_slope(bh & 15) * 64.f);
    size_t base = (size_t)bh * 64 * 16384 + de;
    float st = 0.f;
#pragma unroll 1
    for (int c = 0; c < 64; c++) {
        float kvv = kv[base + (size_t)c * 16384];
        kv[base + (size_t)c * 16384] = st;
        st = dec * st + kvv;
    }
}

// ---------------------------------------------------------------------------
// Group RMSNorm * g_norm_w * sigmoid-gate -> bf16 hi/lo split (fused)
// ---------------------------------------------------------------------------
__global__ void __launch_bounds__(256) gate_norm(
    const float* __restrict__ qkv, const float* __restrict__ gate,
    const float* __restrict__ gw,
    __nv_bfloat16* __restrict__ xhi, __nv_bfloat16* __restrict__ xlo)
{
    int gwid = blockIdx.x * 8 + (threadIdx.x >> 5);
    int lane = threadIdx.x & 31;
    int bt = gwid >> 4, h = gwid & 15;
    const float* orow = qkv + (size_t)bt * 6144 + 4096 + h * 128;
    float4 x = *(const float4*)(orow + lane * 4);
    float ss = x.x * x.x + x.y * x.y + x.z * x.z + x.w * x.w;
#pragma unroll
    for (int off = 16; off >= 1; off >>= 1) ss += __shfl_xor_sync(0xffffffffu, ss, off);
    float r = rsqrtf(ss * (1.f / 128.f) + 1e-6f);
    float4 w  = *(const float4*)(gw + h * 128 + lane * 4);
    size_t idx = (size_t)bt * 2048 + h * 128 + lane * 4;
    float4 gt = *(const float4*)(gate + idx);
    float4 o;
    o.x = x.x * r * w.x * gt.x;
    o.y = x.y * r * w.y * gt.y;
    o.z = x.z * r * w.z * gt.z;
    o.w = x.w * r * w.w * gt.w;
    __nv_bfloat162 h01 = __floats2bfloat162_rn(o.x, o.y);
    __nv_bfloat162 h23 = __floats2bfloat162_rn(o.z, o.w);
    float r0 = o.x - __low2float(h01), r1 = o.y - __high2float(h01);
    float r2 = o.z - __low2float(h23), r3 = o.w - __high2float(h23);
    __nv_bfloat162 l01 = __floats2bfloat162_rn(r0, r1);
    __nv_bfloat162 l23 = __floats2bfloat162_rn(r2, r3);
    uint2 hp, lp;
    hp.x = *(unsigned*)&h01; hp.y = *(unsigned*)&h23;
    lp.x = *(unsigned*)&l01; lp.y = *(unsigned*)&l23;
    *(uint2*)(xhi + idx) = hp;
    *(uint2*)(xlo + idx) = lp;
}

// ---------------------------------------------------------------------------
extern "C" void kernel_launch(void* const* d_in, const int* in_sizes, int n_in,
                              void* d_out, int out_size)
{
    const float* hidden   = (const float*)d_in[0];
    const float* w_qkv    = (const float*)d_in[1];
    const float* q_ln_w   = (const float*)d_in[2];
    const float* k_ln_w   = (const float*)d_in[3];
    const float* g_norm_w = (const float*)d_in[4];
    const float* w_g_proj = (const float*)d_in[5];
    const float* w_dense  = (const float*)d_in[6];
    const int*   pos_ids  = (const int*)d_in[7];
    float* out = (float*)d_out;
    (void)in_sizes; (void)n_in; (void)out_size;

    float *qkv, *gate, *kv, *rope;
    cudaGetSymbolAddress((void**)&qkv,  g_qkv);
    cudaGetSymbolAddress((void**)&gate, g_gate);
    cudaGetSymbolAddress((void**)&kv,   g_kv);
    cudaGetSymbolAddress((void**)&rope, g_rope);
    __nv_bfloat16 *hhi, *hlo, *qwhi, *qwlo, *gwhi, *gwlo, *dwhi, *dwlo, *xhi, *xlo;
    cudaGetSymbolAddress((void**)&hhi,  g_hhi);  cudaGetSymbolAddress((void**)&hlo,  g_hlo);
    cudaGetSymbolAddress((void**)&qwhi, g_qwhi); cudaGetSymbolAddress((void**)&qwlo, g_qwlo);
    cudaGetSymbolAddress((void**)&gwhi, g_gwhi); cudaGetSymbolAddress((void**)&gwlo, g_gwlo);
    cudaGetSymbolAddress((void**)&dwhi, g_dwhi); cudaGetSymbolAddress((void**)&dwlo, g_dwlo);
    cudaGetSymbolAddress((void**)&xhi,  g_xhi);  cudaGetSymbolAddress((void**)&xlo,  g_xlo);

    cudaFuncSetAttribute(kv_outer, cudaFuncAttributeMaxDynamicSharedMemorySize, 67584);
    cudaFuncSetAttribute(gla_gate, cudaFuncAttributeMaxDynamicSharedMemorySize, 93440);
    cudaFuncSetAttribute((const void*)hgemm<false, true, 2>,  cudaFuncAttributeMaxDynamicSharedMemorySize, 2 * STG);
    cudaFuncSetAttribute((const void*)hgemm<false, false, 3>, cudaFuncAttributeMaxDynamicSharedMemorySize, 2 * STG);

    rope_table<<<1024, 256>>>(pos_ids, rope);
    split4h<<<16384, 256>>>(hidden,   hhi,  hlo,  4194304);   // fp16 split
    split4h<<<12288, 256>>>(w_qkv,    qwhi, qwlo, 3145728);   // fp16 split
    split4h<<< 4096, 256>>>(w_g_proj, gwhi, gwlo, 1048576);   // fp16 split
    split4 <<< 4096, 256>>>(w_dense,  dwhi, dwlo, 1048576);   // bf16 split (3-term)

    hgemm<false, true, 2><<<dim3(48, 64), 256, 2 * STG>>>(hhi, hlo, qwhi, qwlo, qkv, 8192, 6144, 2048);
    norm_rope<<<16384, 256>>>(qkv, q_ln_w, k_ln_w, rope);
    kv_outer<<<dim3(64, 32), 256, 67584>>>(qkv, kv);
    scan_states<<<2048, 256>>>(kv);
    // merged: gla_out tiles + gate hgemm tiles (fp16 2-term) in one launch
    gla_gate<<<3072, 256, 93440>>>(qkv, kv, hhi, hlo, gwhi, gwlo, gate);
    gate_norm<<<16384, 256>>>(qkv, gate, g_norm_w, xhi, xlo);
    hgemm<false, false, 3><<<dim3(16, 64), 256, 2 * STG>>>(xhi, xlo, dwhi, dwlo, out, 8192, 2048, 2048);
}

// round 16
// speedup vs baseline: 1.3062x; 1.0599x over previous
#include <cuda_runtime.h>
#include <cuda_bf16.h>
#include <cuda_fp16.h>
#include <math.h>
#include <stdint.h>

// B=2, T=4096, HID=2048, H=16, D=128, ROPE_DIM=64, CHUNK=64, nc=64
typedef unsigned long long ull;

// ---------------------------------------------------------------------------
// Scratch (device globals; allocation is forbidden)
// ---------------------------------------------------------------------------
__device__ float g_qkv [50331648];  // [8192][6144]  q|k|v
__device__ float g_gate[16777216];  // [8192][2048]  sigmoid(gate)
__device__ float g_kv  [33554432];  // [B*H*64][128][128] chunk KV -> in-place S_c
__device__ float g_rope[  524288];  // [8192][64] cos|sin

// 16-bit split buffers (fp16 bits everywhere now; arrays typed bf16 for storage)
__device__ __nv_bfloat16 g_hhi[16777216], g_hlo[16777216];   // hidden (fp16)
__device__ __nv_bfloat16 g_qwhi[12582912], g_qwlo[12582912]; // w_qkv (fp16)
__device__ __nv_bfloat16 g_gwhi[4194304],  g_gwlo[4194304];  // w_g_proj (fp16)
__device__ __nv_bfloat16 g_dwhi[4194304],  g_dwlo[4194304];  // w_dense (fp16)
__device__ __nv_bfloat16 g_xhi[16777216],  g_xlo[16777216];  // gated O (fp16)

__device__ __forceinline__ float head_slope(int h) {
    const float LSCALE = 0.6451712903225806f;   // 1 - 11/31 + 1e-5
    return -exp2f(-0.5f * (float)(h + 1)) * LSCALE;
}

// ---------------------------------------------------------------------------
// Packed f32x2 helpers (attention-side kernels)
// ---------------------------------------------------------------------------
__device__ __forceinline__ ull pk2(float lo, float hi) {
    ull r; asm("mov.b64 %0,{%1,%2};" : "=l"(r) : "f"(lo), "f"(hi)); return r;
}
__device__ __forceinline__ void upk2(ull v, float& lo, float& hi) {
    asm("mov.b64 {%0,%1},%2;" : "=f"(lo), "=f"(hi) : "l"(v));
}
__device__ __forceinline__ void fma2(ull& d, ull a, ull b) {
    asm("fma.rn.f32x2 %0,%1,%2,%0;" : "+l"(d) : "l"(a), "l"(b));
}

// ---------------------------------------------------------------------------
// cp.async / ldmatrix / mma primitives (arch-agnostic: sm_80+)
// ---------------------------------------------------------------------------
__device__ __forceinline__ uint32_t smem_u32(const void* p) {
    uint32_t a;
    asm("{ .reg .u64 t; cvta.to.shared.u64 t, %1; cvt.u32.u64 %0, t; }" : "=r"(a) : "l"(p));
    return a;
}
__device__ __forceinline__ void cpa16(uint32_t dst, const void* src) {
    asm volatile("cp.async.cg.shared.global [%0], [%1], 16;" :: "r"(dst), "l"(src));
}
#define CP_COMMIT() asm volatile("cp.async.commit_group;" ::: "memory")

#define LDSM4(r, a)                                                             \
    asm volatile("ldmatrix.sync.aligned.m8n8.x4.shared.b16 {%0,%1,%2,%3}, [%4];"\
        : "=r"((r)[0]), "=r"((r)[1]), "=r"((r)[2]), "=r"((r)[3]) : "r"(a))

__device__ __forceinline__ void mma16816(float* c, const uint32_t* a, const uint32_t* b) {
    asm volatile("mma.sync.aligned.m16n8k16.row.col.f32.bf16.bf16.f32 "
        "{%0,%1,%2,%3},{%4,%5,%6,%7},{%8,%9},{%0,%1,%2,%3};"
        : "+f"(c[0]), "+f"(c[1]), "+f"(c[2]), "+f"(c[3])
        : "r"(a[0]), "r"(a[1]), "r"(a[2]), "r"(a[3]), "r"(b[0]), "r"(b[1]));
}
__device__ __forceinline__ void mma16816f(float* c, const uint32_t* a, const uint32_t* b) {
    asm volatile("mma.sync.aligned.m16n8k16.row.col.f32.f16.f16.f32 "
        "{%0,%1,%2,%3},{%4,%5,%6,%7},{%8,%9},{%0,%1,%2,%3};"
        : "+f"(c[0]), "+f"(c[1]), "+f"(c[2]), "+f"(c[3])
        : "r"(a[0]), "r"(a[1]), "r"(a[2]), "r"(a[3]), "r"(b[0]), "r"(b[1]));
}

// ---------------------------------------------------------------------------
// fp32 -> fp16 hi/lo split (4 elems/thread); bits stored in bf16 arrays
// ---------------------------------------------------------------------------
__global__ void __launch_bounds__(256) split4h(
    const float* __restrict__ x, __nv_bfloat16* __restrict__ hi_,
    __nv_bfloat16* __restrict__ lo_, int n4)
{
    int i = blockIdx.x * 256 + threadIdx.x;
    if (i >= n4) return;
    float4 v = ((const float4*)x)[i];
    __half2 h01 = __floats2half2_rn(v.x, v.y);
    __half2 h23 = __floats2half2_rn(v.z, v.w);
    float r0 = v.x - __low2float(h01), r1 = v.y - __high2float(h01);
    float r2 = v.z - __low2float(h23), r3 = v.w - __high2float(h23);
    __half2 l01 = __floats2half2_rn(r0, r1);
    __half2 l23 = __floats2half2_rn(r2, r3);
    uint2 hp, lp;
    hp.x = *(unsigned*)&h01; hp.y = *(unsigned*)&h23;
    lp.x = *(unsigned*)&l01; lp.y = *(unsigned*)&l23;
    ((uint2*)hi_)[i] = hp;
    ((uint2*)lo_)[i] = lp;
}

// ---------------------------------------------------------------------------
// HMMA GEMM body: C tile [bm..bm+128) x [bn..bn+128).
// 8 warps x (32m x 64n), K-chunk 32, 2-stage double buffer (80KB smem).
// Per stage (40960B): Ahi@0, Alo@10240, Bhi@20480, Blo@30720; rows 64B data,
// 80B stride. F16: fp16 mma; TERMS=3: hi*hi + lo*hi + hi*lo, TERMS=2 drops hi*lo.
// ---------------------------------------------------------------------------
static constexpr int STG = 40960;
template<bool SIG, bool F16, int TERMS>
__device__ __forceinline__ void hgemm_body(
    int bx, int by, char* smem,
    const __nv_bfloat16* __restrict__ Ahi, const __nv_bfloat16* __restrict__ Alo,
    const __nv_bfloat16* __restrict__ Bhi, const __nv_bfloat16* __restrict__ Blo,
    float* __restrict__ C, int M, int N, int K)
{
    const uint32_t sb = smem_u32(smem);
    const int tid = threadIdx.x, wid = tid >> 5, lane = tid & 31;
    const int bm = by * 128, bn = bx * 128;
    const int wm = (wid & 3) * 32, wn = (wid >> 2) * 64;
    const int NC = K >> 5;

    const char* gAh = (const char*)(Ahi + (size_t)bm * K);
    const char* gAl = (const char*)(Alo + (size_t)bm * K);
    const char* gBh = (const char*)(Bhi + (size_t)bn * K);
    const char* gBl = (const char*)(Blo + (size_t)bn * K);
    const size_t grs = (size_t)K * 2;

    auto load = [&](int c, int s) {
        uint32_t stg = sb + s * STG;
        size_t ko = (size_t)c * 64;
#pragma unroll
        for (int i = 0; i < 2; i++) {
            int u = tid + 256 * i;
            int r = u >> 2; uint32_t q = (uint32_t)(u & 3) * 16;
            uint32_t so = (uint32_t)r * 80 + q;
            size_t go = (size_t)r * grs + ko + q;
            cpa16(stg + so,         gAh + go);
            cpa16(stg + 10240 + so, gAl + go);
            cpa16(stg + 20480 + so, gBh + go);
            if (TERMS == 3) cpa16(stg + 30720 + so, gBl + go);
        }
        CP_COMMIT();
    };

    float acc[2][8][4];
#pragma unroll
    for (int mt = 0; mt < 2; mt++)
#pragma unroll
        for (int nt = 0; nt < 8; nt++)
#pragma unroll
            for (int j = 0; j < 4; j++) acc[mt][nt][j] = 0.f;

    load(0, 0);
    load(1, 1);

    const uint32_t arow = (uint32_t)(wm + (lane & 15));
    const uint32_t brow = (uint32_t)(wn + (lane & 7) + ((lane >> 4) << 3));

    for (int c = 0; c < NC; c++) {
        if (c + 1 < NC) asm volatile("cp.async.wait_group 1;" ::: "memory");
        else            asm volatile("cp.async.wait_group 0;" ::: "memory");
        __syncthreads();
        uint32_t stg = sb + (c & 1) * STG;
#pragma unroll
        for (int s = 0; s < 2; s++) {
            uint32_t colA = (uint32_t)s * 32 + ((lane >> 4) << 4);
            uint32_t colB = (uint32_t)s * 32 + (((lane >> 3) & 1) << 4);
            uint32_t aA = stg + arow * 80 + colA;
            uint32_t aB = stg + 20480 + brow * 80 + colB;
            uint32_t ah[2][4], al[2][4], bb[4][4];
            LDSM4(ah[0], aA);
            LDSM4(ah[1], aA + 16 * 80);
#pragma unroll
            for (int p = 0; p < 4; p++) LDSM4(bb[p], aB + p * 16 * 80);
            // hi*hi
#pragma unroll
            for (int mt = 0; mt < 2; mt++)
#pragma unroll
                for (int nt = 0; nt < 8; nt++) {
                    if (F16) mma16816f(acc[mt][nt], ah[mt], &bb[nt >> 1][(nt & 1) * 2]);
                    else     mma16816 (acc[mt][nt], ah[mt], &bb[nt >> 1][(nt & 1) * 2]);
                }
            // lo*hi
            LDSM4(al[0], aA + 10240);
            LDSM4(al[1], aA + 10240 + 16 * 80);
#pragma unroll
            for (int mt = 0; mt < 2; mt++)
#pragma unroll
                for (int nt = 0; nt < 8; nt++) {
                    if (F16) mma16816f(acc[mt][nt], al[mt], &bb[nt >> 1][(nt & 1) * 2]);
                    else     mma16816 (acc[mt][nt], al[mt], &bb[nt >> 1][(nt & 1) * 2]);
                }
            // hi*lo (3-term only)
            if (TERMS == 3) {
#pragma unroll
                for (int p = 0; p < 4; p++) LDSM4(bb[p], aB + 10240 + p * 16 * 80);
#pragma unroll
                for (int mt = 0; mt < 2; mt++)
#pragma unroll
                    for (int nt = 0; nt < 8; nt++) {
                        if (F16) mma16816f(acc[mt][nt], ah[mt], &bb[nt >> 1][(nt & 1) * 2]);
                        else     mma16816 (acc[mt][nt], ah[mt], &bb[nt >> 1][(nt & 1) * 2]);
                    }
            }
        }
        __syncthreads();
        if (c + 2 < NC) load(c + 2, c & 1);
    }

    const int g = lane >> 2, tg = lane & 3;
#pragma unroll
    for (int mt = 0; mt < 2; mt++) {
        int m0 = bm + wm + mt * 16 + g;
#pragma unroll
        for (int nt = 0; nt < 8; nt++) {
            int n0 = bn + wn + nt * 8 + tg * 2;
            float v0 = acc[mt][nt][0], v1 = acc[mt][nt][1];
            float v2 = acc[mt][nt][2], v3 = acc[mt][nt][3];
            if (SIG) {
                v0 = 1.f / (1.f + expf(-v0)); v1 = 1.f / (1.f + expf(-v1));
                v2 = 1.f / (1.f + expf(-v2)); v3 = 1.f / (1.f + expf(-v3));
            }
            float2* p0 = (float2*)(C + (size_t)m0 * N + n0);
            float2* p1 = (float2*)(C + (size_t)(m0 + 8) * N + n0);
            *p0 = make_float2(v0, v1);
            *p1 = make_float2(v2, v3);
        }
    }
}

template<bool SIG, bool F16, int TERMS>
__global__ void __launch_bounds__(256, 2) hgemm(
    const __nv_bfloat16* __restrict__ Ahi, const __nv_bfloat16* __restrict__ Alo,
    const __nv_bfloat16* __restrict__ Bhi, const __nv_bfloat16* __restrict__ Blo,
    float* __restrict__ C, int M, int N, int K)
{
    extern __shared__ char smem[];
    hgemm_body<SIG, F16, TERMS>(blockIdx.x, blockIdx.y, smem, Ahi, Alo, Bhi, Blo, C, M, N, K);
}

// ---------------------------------------------------------------------------
// gla_out body: O = (mask .* QK^T) V + diag(exp(g*(i+1))) Q S_c  for tile (c,bh)
// ---------------------------------------------------------------------------
__device__ __forceinline__ void gla_body(
    int c, int bh, char* smraw, float* __restrict__ qkv, const float* __restrict__ S)
{
    float* sm  = (float*)smraw;
    float* Qs  = sm;
    float* KVs = sm + 8448;
    float* Att = sm + 16896;
    float* St  = sm + 21248;
    int b = bh >> 4, h = bh & 15;
    float g = head_slope(h);
    int tid = threadIdx.x;

    int li = tid >> 2, lc = (tid & 3) * 32;
    const float* qrowL = qkv + (size_t)(b * 4096 + c * 64 + li) * 6144 + h * 128;
#pragma unroll
    for (int u = 0; u < 8; u++) {
        *(float4*)&Qs [li * 132 + lc + u * 4] = *(const float4*)(qrowL + lc + u * 4);
        *(float4*)&KVs[li * 132 + lc + u * 4] = *(const float4*)(qrowL + 2048 + lc + u * 4);
    }
    __syncthreads();

    int tx = tid & 15, ty = tid >> 4;
    {
        int i0 = ty * 4, j0 = tx * 4;
        float a[4][4];
#pragma unroll
        for (int ii = 0; ii < 4; ii++)
#pragma unroll
            for (int jj = 0; jj < 4; jj++) a[ii][jj] = 0.f;
        for (int d = 0; d < 128; d += 4) {
            float4 qv[4], kv4[4];
#pragma unroll
            for (int ii = 0; ii < 4; ii++) qv[ii]  = *(const float4*)&Qs [(i0 + ii) * 132 + d];
#pragma unroll
            for (int jj = 0; jj < 4; jj++) kv4[jj] = *(const float4*)&KVs[(j0 + jj) * 132 + d];
#pragma unroll
            for (int ii = 0; ii < 4; ii++)
#pragma unroll
                for (int jj = 0; jj < 4; jj++)
                    a[ii][jj] += qv[ii].x * kv4[jj].x + qv[ii].y * kv4[jj].y
                               + qv[ii].z * kv4[jj].z + qv[ii].w * kv4[jj].w;
        }
#pragma unroll
        for (int ii = 0; ii < 4; ii++)
#pragma unroll
            for (int jj = 0; jj < 4; jj++) {
                int i = i0 + ii, j = j0 + jj;
                Att[i * 68 + j] = (i >= j) ? a[ii][jj] * expf(g * (float)(i - j)) : 0.f;
            }
    }
    __syncthreads();
#pragma unroll
    for (int u = 0; u < 8; u++)
        *(float4*)&KVs[li * 132 + lc + u * 4] = *(const float4*)(qrowL + 4096 + lc + u * 4);

    int i0 = ty * 4, e0 = tx * 8;
    ull acc[4][4];
#pragma unroll
    for (int ii = 0; ii < 4; ii++)
#pragma unroll
        for (int j = 0; j < 4; j++) acc[ii][j] = 0ull;

    size_t sbase2 = (size_t)(bh * 64 + c) * 16384;
    int sr = tid >> 4, sc = (tid & 15) * 8;
    for (int dt = 0; dt < 8; dt++) {
        __syncthreads();
        *(float4*)&St[sr * 132 + sc]     = *(const float4*)(S + sbase2 + (size_t)(dt * 16 + sr) * 128 + sc);
        *(float4*)&St[sr * 132 + sc + 4] = *(const float4*)(S + sbase2 + (size_t)(dt * 16 + sr) * 128 + sc + 4);
        __syncthreads();
#pragma unroll
        for (int d = 0; d < 16; d++) {
            float4 s0 = *(const float4*)&St[d * 132 + e0];
            float4 s1 = *(const float4*)&St[d * 132 + e0 + 4];
            ull ss[4] = { pk2(s0.x, s0.y), pk2(s0.z, s0.w), pk2(s1.x, s1.y), pk2(s1.z, s1.w) };
#pragma unroll
            for (int ii = 0; ii < 4; ii++) {
                float q = Qs[(i0 + ii) * 132 + dt * 16 + d];
                ull aa = pk2(q, q);
#pragma unroll
                for (int j = 0; j < 4; j++) fma2(acc[ii][j], aa, ss[j]);
            }
        }
    }
#pragma unroll
    for (int ii = 0; ii < 4; ii++) {
        float qd = expf(g * (float)(i0 + ii + 1));
#pragma unroll
        for (int j = 0; j < 4; j++) {
            float lo, hi; upk2(acc[ii][j], lo, hi);
            acc[ii][j] = pk2(lo * qd, hi * qd);
        }
    }
#pragma unroll 4
    for (int j = 0; j < 64; j++) {
        float4 v0 = *(const float4*)&KVs[j * 132 + e0];
        float4 v1 = *(const float4*)&KVs[j * 132 + e0 + 4];
        ull vv[4] = { pk2(v0.x, v0.y), pk2(v0.z, v0.w), pk2(v1.x, v1.y), pk2(v1.z, v1.w) };
#pragma unroll
        for (int ii = 0; ii < 4; ii++) {
            float a = Att[(i0 + ii) * 68 + j];
            ull aa = pk2(a, a);
#pragma unroll
            for (int jj = 0; jj < 4; jj++) fma2(acc[ii][jj], aa, vv[jj]);
        }
    }
#pragma unroll
    for (int ii = 0; ii < 4; ii++) {
        float o[8];
#pragma unroll
        for (int j = 0; j < 4; j++) upk2(acc[ii][j], o[2 * j], o[2 * j + 1]);
        float* orow = qkv + (size_t)(b * 4096 + c * 64 + i0 + ii) * 6144 + 4096 + h * 128 + e0;
        *(float4*)orow       = make_float4(o[0], o[1], o[2], o[3]);
        *(float4*)(orow + 4) = make_float4(o[4], o[5], o[6], o[7]);
    }
}

// ---------------------------------------------------------------------------
// MERGED kernel: 3072 blocks. bid%3==2 -> gate hgemm tile (tensor pipe, fp16
// 2-term); else -> gla_out tile (fma/L1 pipes).
// ---------------------------------------------------------------------------
__global__ void __launch_bounds__(256, 2) gla_gate(
    float* __restrict__ qkv, const float* __restrict__ S,
    const __nv_bfloat16* __restrict__ Ahi, const __nv_bfloat16* __restrict__ Alo,
    const __nv_bfloat16* __restrict__ Bhi, const __nv_bfloat16* __restrict__ Blo,
    float* __restrict__ gate)
{
    extern __shared__ char smem[];
    int bid = blockIdx.x;
    if (bid % 3 == 2) {
        int q = bid / 3;                        // 0..1023
        hgemm_body<true, true, 2>(q & 15, q >> 4, smem, Ahi, Alo, Bhi, Blo, gate, 8192, 2048, 2048);
    } else {
        int gidx = (bid / 3) * 2 + (bid % 3);   // 0..2047
        gla_body(gidx & 63, gidx >> 6, smem, qkv, S);
    }
}

// ---------------------------------------------------------------------------
// RoPE cos/sin table (fp64 angles)
// ---------------------------------------------------------------------------
__global__ void rope_table(const int* __restrict__ pos, float* __restrict__ rope)
{
    int idx = blockIdx.x * 256 + threadIdx.x;
    int bt = idx >> 5, i = idx & 31;
    double invf = pow(10000.0, -(double)(2 * i) / 64.0);
    double ang  = (double)pos[bt] * invf;
    double sd, cd; sincos(ang, &sd, &cd);
    rope[bt * 64 + i]      = (float)cd;
    rope[bt * 64 + 32 + i] = (float)sd;
}

// ---------------------------------------------------------------------------
// Per-head RMSNorm + RoPE on q,k in place (warp per (bt,h)); q *= D^-1/2.
// ---------------------------------------------------------------------------
__global__ void __launch_bounds__(256) norm_rope(
    float* __restrict__ qkv, const float* __restrict__ qw,
    const float* __restrict__ kw, const float* __restrict__ rope)
{
    int gw   = blockIdx.x * 8 + (threadIdx.x >> 5);
    int lane = threadIdx.x & 31;
    int bt = gw >> 4, h = gw & 15;
    float* qrow = qkv + (size_t)bt * 6144 + h * 128;
    const float* rc = rope + bt * 64;

    float c4[4], s4[4];
    if (lane < 16) {
#pragma unroll
        for (int m = 0; m < 4; m++) {
            int fi = (lane * 4 + m) & 31;
            c4[m] = rc[fi]; s4[m] = rc[32 + fi];
        }
    }
    float sgn = (lane < 8) ? -1.f : 1.f;

#pragma unroll
    for (int pass = 0; pass < 2; pass++) {
        float* row = qrow + pass * 2048;
        const float* wv = pass ? kw : qw;
        float4 x = *(float4*)(row + lane * 4);
        float ss = x.x * x.x + x.y * x.y + x.z * x.z + x.w * x.w;
#pragma unroll
        for (int off = 16; off >= 1; off >>= 1) ss += __shfl_xor_sync(0xffffffffu, ss, off);
        float r = rsqrtf(ss * (1.f / 128.f) + 1e-6f);
        float4 w4 = *(const float4*)(wv + lane * 4);
        x.x *= r * w4.x; x.y *= r * w4.y; x.z *= r * w4.z; x.w *= r * w4.w;
        float px = __shfl_xor_sync(0xffffffffu, x.x, 8);
        float py = __shfl_xor_sync(0xffffffffu, x.y, 8);
        float pz = __shfl_xor_sync(0xffffffffu, x.z, 8);
        float pw = __shfl_xor_sync(0xffffffffu, x.w, 8);
        if (lane < 16) {
            x.x = x.x * c4[0] + sgn * px * s4[0];
            x.y = x.y * c4[1] + sgn * py * s4[1];
            x.z = x.z * c4[2] + sgn * pz * s4[2];
            x.w = x.w * c4[3] + sgn * pw * s4[3];
        }
        if (pass == 0) {
            const float qs = 0.08838834764831845f;
            x.x *= qs; x.y *= qs; x.z *= qs; x.w *= qs;
        }
        *(float4*)(row + lane * 4) = x;
    }
}

// ---------------------------------------------------------------------------
// Per-chunk decayed KV outer product (f32x2)
// ---------------------------------------------------------------------------
__global__ void __launch_bounds__(256) kv_outer(
    const float* __restrict__ qkv, float* __restrict__ kv)
{
    extern __shared__ __align__(16) float sm[];
    float* Ks = sm;
    float* Vs = sm + 64 * 132;
    int c = blockIdx.x, bh = blockIdx.y;
    int b = bh >> 4, h = bh & 15;
    float g = head_slope(h);
    int tid = threadIdx.x;

    int li = tid >> 2, lc = (tid & 3) * 32;
    const float* krow = qkv + (size_t)(b * 4096 + c * 64 + li) * 6144 + 2048 + h * 128;
    float kd = expf(g * (float)(63 - li));
#pragma unroll
    for (int u = 0; u < 8; u++) {
        float4 kk = *(const float4*)(krow + lc + u * 4);
        kk.x *= kd; kk.y *= kd; kk.z *= kd; kk.w *= kd;
        *(float4*)&Ks[li * 132 + lc + u * 4] = kk;
        *(float4*)&Vs[li * 132 + lc + u * 4] = *(const float4*)(krow + 2048 + lc + u * 4);
    }
    __syncthreads();

    int tx = tid & 15, ty = tid >> 4;
    int d0 = ty * 8, e0 = tx * 8;
    ull acc[8][4];
#pragma unroll
    for (int i = 0; i < 8; i++)
#pragma unroll
        for (int j = 0; j < 4; j++) acc[i][j] = 0ull;

    for (int i = 0; i < 64; i++) {
        float4 k0 = *(const float4*)&Ks[i * 132 + d0];
        float4 k1 = *(const float4*)&Ks[i * 132 + d0 + 4];
        float4 v0 = *(const float4*)&Vs[i * 132 + e0];
        float4 v1 = *(const float4*)&Vs[i * 132 + e0 + 4];
        ull vv[4] = { pk2(v0.x, v0.y), pk2(v0.z, v0.w), pk2(v1.x, v1.y), pk2(v1.z, v1.w) };
        float km[8] = { k0.x, k0.y, k0.z, k0.w, k1.x, k1.y, k1.z, k1.w };
#pragma unroll
        for (int di = 0; di < 8; di++) {
            ull aa = pk2(km[di], km[di]);
#pragma unroll
            for (int j = 0; j < 4; j++) fma2(acc[di][j], aa, vv[j]);
        }
    }
    size_t base = (size_t)(bh * 64 + c) * 16384;
#pragma unroll
    for (int di = 0; di < 8; di++) {
        float o[8];
#pragma unroll
        for (int j = 0; j < 4; j++) upk2(acc[di][j], o[2 * j], o[2 * j + 1]);
        float* op = kv + base + (size_t)(d0 + di) * 128 + e0;
        *(float4*)op       = make_float4(o[0], o[1], o[2], o[3]);
        *(float4*)(op + 4) = make_float4(o[4], o[5], o[6], o[7]);
    }
}

// ---------------------------------------------------------------------------
// In-place decay scan over kv: writes pre-state S_c
// ---------------------------------------------------------------------------
__global__ void __launch_bounds__(256) scan_states(float* __restrict__ kv)
{
    int t  = blockIdx.x * 256 + threadIdx.x;
    int bh = t >> 14, de = t & 16383;
    float dec = expf(head_slope(bh & 15) * 64.f);
    size_t base = (size_t)bh * 64 * 16384 + de;
    float st = 0.f;
#pragma unroll 1
    for (int c = 0; c < 64; c++) {
        float kvv = kv[base + (size_t)c * 16384];
        kv[base + (size_t)c * 16384] = st;
        st = dec * st + kvv;
    }
}

// ---------------------------------------------------------------------------
// Group RMSNorm * g_norm_w * sigmoid-gate -> fp16 hi/lo split (fused)
// ---------------------------------------------------------------------------
__global__ void __launch_bounds__(256) gate_norm(
    const float* __restrict__ qkv, const float* __restrict__ gate,
    const float* __restrict__ gw,
    __nv_bfloat16* __restrict__ xhi, __nv_bfloat16* __restrict__ xlo)
{
    int gwid = blockIdx.x * 8 + (threadIdx.x >> 5);
    int lane = threadIdx.x & 31;
    int bt = gwid >> 4, h = gwid & 15;
    const float* orow = qkv + (size_t)bt * 6144 + 4096 + h * 128;
    float4 x = *(const float4*)(orow + lane * 4);
    float ss = x.x * x.x + x.y * x.y + x.z * x.z + x.w * x.w;
#pragma unroll
    for (int off = 16; off >= 1; off >>= 1) ss += __shfl_xor_sync(0xffffffffu, ss, off);
    float r = rsqrtf(ss * (1.f / 128.f) + 1e-6f);
    float4 w  = *(const float4*)(gw + h * 128 + lane * 4);
    size_t idx = (size_t)bt * 2048 + h * 128 + lane * 4;
    float4 gt = *(const float4*)(gate + idx);
    float4 o;
    o.x = x.x * r * w.x * gt.x;
    o.y = x.y * r * w.y * gt.y;
    o.z = x.z * r * w.z * gt.z;
    o.w = x.w * r * w.w * gt.w;
    __half2 h01 = __floats2half2_rn(o.x, o.y);
    __half2 h23 = __floats2half2_rn(o.z, o.w);
    float r0 = o.x - __low2float(h01), r1 = o.y - __high2float(h01);
    float r2 = o.z - __low2float(h23), r3 = o.w - __high2float(h23);
    __half2 l01 = __floats2half2_rn(r0, r1);
    __half2 l23 = __floats2half2_rn(r2, r3);
    uint2 hp, lp;
    hp.x = *(unsigned*)&h01; hp.y = *(unsigned*)&h23;
    lp.x = *(unsigned*)&l01; lp.y = *(unsigned*)&l23;
    *(uint2*)(xhi + idx) = hp;
    *(uint2*)(xlo + idx) = lp;
}

// ---------------------------------------------------------------------------
extern "C" void kernel_launch(void* const* d_in, const int* in_sizes, int n_in,
                              void* d_out, int out_size)
{
    const float* hidden   = (const float*)d_in[0];
    const float* w_qkv    = (const float*)d_in[1];
    const float* q_ln_w   = (const float*)d_in[2];
    const float* k_ln_w   = (const float*)d_in[3];
    const float* g_norm_w = (const float*)d_in[4];
    const float* w_g_proj = (const float*)d_in[5];
    const float* w_dense  = (const float*)d_in[6];
    const int*   pos_ids  = (const int*)d_in[7];
    float* out = (float*)d_out;
    (void)in_sizes; (void)n_in; (void)out_size;

    float *qkv, *gate, *kv, *rope;
    cudaGetSymbolAddress((void**)&qkv,  g_qkv);
    cudaGetSymbolAddress((void**)&gate, g_gate);
    cudaGetSymbolAddress((void**)&kv,   g_kv);
    cudaGetSymbolAddress((void**)&rope, g_rope);
    __nv_bfloat16 *hhi, *hlo, *qwhi, *qwlo, *gwhi, *gwlo, *dwhi, *dwlo, *xhi, *xlo;
    cudaGetSymbolAddress((void**)&hhi,  g_hhi);  cudaGetSymbolAddress((void**)&hlo,  g_hlo);
    cudaGetSymbolAddress((void**)&qwhi, g_qwhi); cudaGetSymbolAddress((void**)&qwlo, g_qwlo);
    cudaGetSymbolAddress((void**)&gwhi, g_gwhi); cudaGetSymbolAddress((void**)&gwlo, g_gwlo);
    cudaGetSymbolAddress((void**)&dwhi, g_dwhi); cudaGetSymbolAddress((void**)&dwlo, g_dwlo);
    cudaGetSymbolAddress((void**)&xhi,  g_xhi);  cudaGetSymbolAddress((void**)&xlo,  g_xlo);

    cudaFuncSetAttribute(kv_outer, cudaFuncAttributeMaxDynamicSharedMemorySize, 67584);
    cudaFuncSetAttribute(gla_gate, cudaFuncAttributeMaxDynamicSharedMemorySize, 93440);
    cudaFuncSetAttribute((const void*)hgemm<false, true, 2>, cudaFuncAttributeMaxDynamicSharedMemorySize, 2 * STG);

    rope_table<<<1024, 256>>>(pos_ids, rope);
    split4h<<<16384, 256>>>(hidden,   hhi,  hlo,  4194304);
    split4h<<<12288, 256>>>(w_qkv,    qwhi, qwlo, 3145728);
    split4h<<< 4096, 256>>>(w_g_proj, gwhi, gwlo, 1048576);
    split4h<<< 4096, 256>>>(w_dense,  dwhi, dwlo, 1048576);

    hgemm<false, true, 2><<<dim3(48, 64), 256, 2 * STG>>>(hhi, hlo, qwhi, qwlo, qkv, 8192, 6144, 2048);
    norm_rope<<<16384, 256>>>(qkv, q_ln_w, k_ln_w, rope);
    kv_outer<<<dim3(64, 32), 256, 67584>>>(qkv, kv);
    scan_states<<<2048, 256>>>(kv);
    // merged: gla_out tiles + gate hgemm tiles (fp16 2-term) in one launch
    gla_gate<<<3072, 256, 93440>>>(qkv, kv, hhi, hlo, gwhi, gwlo, gate);
    gate_norm<<<16384, 256>>>(qkv, gate, g_norm_w, xhi, xlo);
    hgemm<false, true, 2><<<dim3(16, 64), 256, 2 * STG>>>(xhi, xlo, dwhi, dwlo, out, 8192, 2048, 2048);
}